// round 9
// baseline (speedup 1.0000x reference)
#include <cuda_runtime.h>
#include <cuda_bf16.h>
#include <cstdint>

// ============================================================
// Actor MLP via warp-level mma.sync (bf16x3 split precision).
// R9: NO shared memory, NO barriers, NO cp.async. Each warp
// free-runs all 101 layers; weights read per-fragment from a
// frag-permuted global table via ld.global.nc.v4 (L1-cached,
// 16x reuse per SM). Activations live in registers end-to-end.
// ============================================================

#define NF 13          // n-fragments (8 wide)  -> N = 104
#define KF 7           // k-fragments (16 wide) -> K = 112
#define CHUNK 49152    // per-layer chunk stride; weights 46592B + bias 416B
#define BIASOFF 46592  // bias offset inside chunk
#define NLAYERS 101    // layer 0 = W_in, layers 1..100 = hidden

__device__ __align__(16) unsigned char g_WP[NLAYERS * CHUNK];    // ~4.97 MB
__device__ __align__(16) float2 g_WOUTP[NF * 4];

// ---- helpers ----
__device__ __forceinline__ float bf16lo(uint32_t p) { return __uint_as_float(p << 16); }
__device__ __forceinline__ float bf16hi(uint32_t p) { return __uint_as_float(p & 0xFFFF0000u); }
__device__ __forceinline__ uint32_t packbf(float lo_val, float hi_val) {
    uint32_t r;
    asm("cvt.rn.bf16x2.f32 %0, %1, %2;" : "=r"(r) : "f"(hi_val), "f"(lo_val));
    return r;
}
// read-only global load, L1-cached (weights table is immutable during launch)
__device__ __forceinline__ uint4 ldg128(const void* p) {
    uint4 v;
    asm("ld.global.nc.v4.u32 {%0,%1,%2,%3}, [%4];"
        : "=r"(v.x), "=r"(v.y), "=r"(v.z), "=r"(v.w) : "l"(p));
    return v;
}
__device__ __forceinline__ float2 ldg64f(const void* p) {
    float2 v;
    asm("ld.global.nc.v2.f32 {%0,%1}, [%2];" : "=f"(v.x), "=f"(v.y) : "l"(p));
    return v;
}

__device__ __forceinline__ void hmma(float* d, const uint32_t* a, uint32_t b0, uint32_t b1) {
    asm("mma.sync.aligned.m16n8k16.row.col.f32.bf16.bf16.f32 "
        "{%0,%1,%2,%3}, {%4,%5,%6,%7}, {%8,%9}, {%0,%1,%2,%3};"
        : "+f"(d[0]), "+f"(d[1]), "+f"(d[2]), "+f"(d[3])
        : "r"(a[0]), "r"(a[1]), "r"(a[2]), "r"(a[3]), "r"(b0), "r"(b1));
}
// leaky via slct: (v >= 0) ? v : 0.01v  -- value-identical, 2 instr
__device__ __forceinline__ float leaky(float v) {
    float m = 0.01f * v, r;
    asm("slct.f32.f32 %0, %1, %2, %3;" : "=f"(r) : "f"(v), "f"(m), "f"(v));
    return r;
}

// ============================================================
// prep: fragment-permuted weights, hi/lo interleaved per lane:
//   uint4 @ (L*CHUNK + ((kf*NF+nf)*32 + lane)*16) =
//     { hi(k,k+1), hi(k+8,k+9), lo(k,k+1), lo(k+8,k+9) }
//   with n = nf*8 + lane/4, k = kf*16 + 2*(lane%4)
// bias (float2 per (nf,q)) @ L*CHUNK + BIASOFF + (nf*4+q)*8
// ============================================================
#define NWT (NLAYERS * KF * NF * 32)
__global__ void prep(const float* __restrict__ W_in, const float* __restrict__ b_in,
                     const float* __restrict__ Ws, const float* __restrict__ bs,
                     const float* __restrict__ W_out) {
    int t = blockIdx.x * 256 + threadIdx.x;
    if (t < NWT) {
        int L = t / (KF * NF * 32);
        int r = t % (KF * NF * 32);
        int kf = r / (NF * 32);
        int r2 = r % (NF * 32);
        int nf = r2 / 32, lane = r2 % 32;
        int n = nf * 8 + (lane >> 2);
        int k = kf * 16 + 2 * (lane & 3);
        float v[4];  // (k, k+1, k+8, k+9)
#pragma unroll
        for (int e = 0; e < 4; e++) {
            int kk = k + (e & 1) + (e >> 1) * 8;
            float w = 0.0f;
            if (L == 0) {
                if (kk < 64 && n < 100) w = W_in[kk * 100 + n];
            } else {
                if (kk < 100 && n < 100) w = Ws[((size_t)(L - 1) * 100 + kk) * 100 + n];
            }
            v[e] = w;
        }
        uint32_t hp0 = packbf(v[0], v[1]);
        uint32_t hp1 = packbf(v[2], v[3]);
        uint32_t lp0 = packbf(v[0] - bf16lo(hp0), v[1] - bf16hi(hp0));
        uint32_t lp1 = packbf(v[2] - bf16lo(hp1), v[3] - bf16hi(hp1));
        size_t off = (size_t)L * CHUNK + ((size_t)(kf * NF + nf) * 32 + lane) * 16;
        *(uint4*)(g_WP + off) = make_uint4(hp0, hp1, lp0, lp1);
        return;
    }
    t -= NWT;
    if (t < NLAYERS * NF * 4) {
        int m = t / (NF * 4);
        int r = t % (NF * 4);
        int nf = r / 4, q = r % 4;
        int c = nf * 8 + 2 * q;
        float b0 = (c < 100)     ? (m == 0 ? b_in[c]     : bs[(m - 1) * 100 + c])     : 0.0f;
        float b1 = (c + 1 < 100) ? (m == 0 ? b_in[c + 1] : bs[(m - 1) * 100 + c + 1]) : 0.0f;
        *(float2*)(g_WP + (size_t)m * CHUNK + BIASOFF + (size_t)r * 8) = make_float2(b0, b1);
        return;
    }
    t -= NLAYERS * NF * 4;
    if (t < NF * 4) {
        int nf = t / 4, q = t % 4;
        int c = nf * 8 + 2 * q;
        g_WOUTP[t] = make_float2(c < 100 ? W_out[c] : 0.0f,
                                 c + 1 < 100 ? W_out[c + 1] : 0.0f);
    }
}

// ============================================================
// main kernel: 256 threads (8 warps x 16 samples = 128/block),
// zero smem, zero block-level synchronization.
// ============================================================
__global__ void __launch_bounds__(256, 2)
actor(const float* __restrict__ x, const float* __restrict__ b_out,
      float* __restrict__ out, int nsamples) {
    const int tid = threadIdx.x, lane = tid & 31, warp = tid >> 5;
    const int s0 = blockIdx.x * 128 + warp * 16;
    const int r = lane >> 2, kc = 2 * (lane & 3);
    const bool vlo = (s0 + r) < nsamples;
    const bool vhi = (s0 + r + 8) < nsamples;

    // ---- layer-0 A fragments straight from x (K=64 -> kf 0..3) ----
    uint32_t Ah[KF][4], Al[KF][4];
    {
        const float* xb = x + (size_t)s0 * 64;
#pragma unroll
        for (int kf = 0; kf < 4; kf++) {
            int k = kf * 16 + kc;
            float2 p00 = vlo ? *(const float2*)(xb + (size_t)r * 64 + k)           : make_float2(0.f, 0.f);
            float2 p01 = vlo ? *(const float2*)(xb + (size_t)r * 64 + k + 8)       : make_float2(0.f, 0.f);
            float2 p10 = vhi ? *(const float2*)(xb + (size_t)(r + 8) * 64 + k)     : make_float2(0.f, 0.f);
            float2 p11 = vhi ? *(const float2*)(xb + (size_t)(r + 8) * 64 + k + 8) : make_float2(0.f, 0.f);
            uint32_t h0 = packbf(p00.x, p00.y), h1 = packbf(p10.x, p10.y);
            uint32_t h2 = packbf(p01.x, p01.y), h3 = packbf(p11.x, p11.y);
            Ah[kf][0] = h0; Ah[kf][1] = h1; Ah[kf][2] = h2; Ah[kf][3] = h3;
            Al[kf][0] = packbf(p00.x - bf16lo(h0), p00.y - bf16hi(h0));
            Al[kf][1] = packbf(p10.x - bf16lo(h1), p10.y - bf16hi(h1));
            Al[kf][2] = packbf(p01.x - bf16lo(h2), p01.y - bf16hi(h2));
            Al[kf][3] = packbf(p11.x - bf16lo(h3), p11.y - bf16hi(h3));
        }
#pragma unroll
        for (int kf = 4; kf < KF; kf++) {
            Ah[kf][0] = Ah[kf][1] = Ah[kf][2] = Ah[kf][3] = 0u;
            Al[kf][0] = Al[kf][1] = Al[kf][2] = Al[kf][3] = 0u;
        }
    }

    float po0 = 0.0f, po1 = 0.0f;  // head partials (rows r, r+8)

#pragma unroll 1
    for (int m = 0; m <= 100; m++) {
        const unsigned char* wb = g_WP + (size_t)m * CHUNK;

        // D initialized to bias (from the layer chunk, L1-hot)
        float D[NF][4];
        {
            const unsigned char* ba = wb + BIASOFF + (size_t)(lane & 3) * 8;
#pragma unroll
            for (int nf = 0; nf < NF; nf++) {
                float2 bv = ldg64f(ba + (size_t)nf * 32);
                D[nf][0] = bv.x; D[nf][1] = bv.y; D[nf][2] = bv.x; D[nf][3] = bv.y;
            }
        }

        // ---- 3-product bf16 GEMM, weights via ldg128 (L1) ----
        // per-accumulator order unchanged: hi, lo*Whi, hi*Wlo per kf
#pragma unroll
        for (int kf = 0; kf < KF; kf++) {
            const unsigned char* ad = wb + (size_t)(kf * NF) * 512 + (size_t)lane * 16;
#pragma unroll
            for (int p = 0; p < 6; p++) {
                uint4 w0 = ldg128(ad);
                uint4 w1 = ldg128(ad + 512);
                float* D0 = D[2 * p];
                float* D1 = D[2 * p + 1];
                hmma(D0, Ah[kf], w0.x, w0.y);
                hmma(D1, Ah[kf], w1.x, w1.y);
                hmma(D0, Al[kf], w0.x, w0.y);
                hmma(D1, Al[kf], w1.x, w1.y);
                hmma(D0, Ah[kf], w0.z, w0.w);
                hmma(D1, Ah[kf], w1.z, w1.w);
                ad += 1024;
            }
            {   // nf = 12 (single)
                uint4 w0 = ldg128(ad);
                hmma(D[12], Ah[kf], w0.x, w0.y);
                hmma(D[12], Al[kf], w0.x, w0.y);
                hmma(D[12], Ah[kf], w0.z, w0.w);
            }
        }

        // ---- epilogue (registers only) ----
        if (m < 100) {
#pragma unroll
            for (int nf = 0; nf < NF; nf++) {
                D[nf][0] = leaky(D[nf][0]);
                D[nf][1] = leaky(D[nf][1]);
                D[nf][2] = leaky(D[nf][2]);
                D[nf][3] = leaky(D[nf][3]);
            }
#pragma unroll
            for (int t2 = 0; t2 < 6; t2++) {
                const float* d0 = D[2 * t2];
                const float* d1 = D[2 * t2 + 1];
                uint32_t h0 = packbf(d0[0], d0[1]), h1 = packbf(d0[2], d0[3]);
                uint32_t h2 = packbf(d1[0], d1[1]), h3 = packbf(d1[2], d1[3]);
                Ah[t2][0] = h0; Ah[t2][1] = h1; Ah[t2][2] = h2; Ah[t2][3] = h3;
                Al[t2][0] = packbf(d0[0] - bf16lo(h0), d0[1] - bf16hi(h0));
                Al[t2][1] = packbf(d0[2] - bf16lo(h1), d0[3] - bf16hi(h1));
                Al[t2][2] = packbf(d1[0] - bf16lo(h2), d1[1] - bf16hi(h2));
                Al[t2][3] = packbf(d1[2] - bf16lo(h3), d1[3] - bf16hi(h3));
            }
            {   // t2 = 6: cols 96..103 from D[12]; 104..111 zero-pad
                const float* d0 = D[12];
                uint32_t h0 = packbf(d0[0], d0[1]), h1 = packbf(d0[2], d0[3]);
                Ah[6][0] = h0; Ah[6][1] = h1; Ah[6][2] = 0u; Ah[6][3] = 0u;
                Al[6][0] = packbf(d0[0] - bf16lo(h0), d0[1] - bf16hi(h0));
                Al[6][1] = packbf(d0[2] - bf16lo(h1), d0[3] - bf16hi(h1));
                Al[6][2] = 0u; Al[6][3] = 0u;
            }
        } else {
            // head: h = leaky(layer-100 out), partial dot with W_out
#pragma unroll
            for (int nf = 0; nf < NF; nf++) {
                float2 w = g_WOUTP[nf * 4 + (lane & 3)];
                po0 += leaky(D[nf][0]) * w.x + leaky(D[nf][1]) * w.y;
                po1 += leaky(D[nf][2]) * w.x + leaky(D[nf][3]) * w.y;
            }
        }
    }

    // ---- head reduce across the 4 lanes sharing a row ----
    po0 += __shfl_xor_sync(0xffffffff, po0, 1);
    po0 += __shfl_xor_sync(0xffffffff, po0, 2);
    po1 += __shfl_xor_sync(0xffffffff, po1, 1);
    po1 += __shfl_xor_sync(0xffffffff, po1, 2);
    if ((lane & 3) == 0) {
        float bo = b_out[0];
        if (vlo) out[s0 + r]     = tanhf(po0 + bo) * 4.5f + 5.5f;
        if (vhi) out[s0 + r + 8] = tanhf(po1 + bo) * 4.5f + 5.5f;
    }
}

extern "C" void kernel_launch(void* const* d_in, const int* in_sizes, int n_in,
                              void* d_out, int out_size) {
    const float* x     = (const float*)d_in[0];
    const float* W_in  = (const float*)d_in[1];
    const float* b_in  = (const float*)d_in[2];
    const float* Ws    = (const float*)d_in[3];
    const float* bs    = (const float*)d_in[4];
    const float* W_out = (const float*)d_in[5];
    const float* b_out = (const float*)d_in[6];
    float* out = (float*)d_out;

    int nsamples = in_sizes[0] / 64;
    int nblocks  = (nsamples + 127) / 128;

    const int PREP_TOTAL = NWT + NLAYERS * NF * 4 + NF * 4;
    prep<<<(PREP_TOTAL + 255) / 256, 256>>>(W_in, b_in, Ws, bs, W_out);

    actor<<<nblocks, 256>>>(x, b_out, out, nsamples);
}

// round 10
// speedup vs baseline: 1.5472x; 1.5472x over previous
#include <cuda_runtime.h>
#include <cuda_fp16.h>
#include <cstdint>

// ============================================================
// Actor MLP via warp-level mma.sync, fp16 two-product scheme:
//   D = Af16 * Wh + Af16 * Wl   (Wh+Wl = W to ~22 bits, f16)
// A quantized to f16 each layer (~2^-11); W error negligible.
// Each warp owns 16 samples; activations in registers for all
// 101 layers. Weights cp.async double-buffered, frag-permuted,
// Wh/Wl interleaved (one LDS.128 per (kf,nf)). Single barrier
// per layer; bias stored inside the weight chunk.
// ============================================================

#define NF 13          // n-fragments (8 wide)  -> N = 104
#define KF 7           // k-fragments (16 wide) -> K = 112
#define CHUNK 49152    // per-layer chunk stride; weights 46592B + bias 416B
#define BIASOFF 46592  // bias offset inside chunk
#define NLAYERS 101    // layer 0 = W_in, layers 1..100 = hidden

__device__ __align__(16) unsigned char g_WP[NLAYERS * CHUNK];    // ~4.97 MB
__device__ __align__(16) float2 g_WOUTP[NF * 4];

// ---- helpers ----
__device__ __forceinline__ uint32_t smem_u32(const void* p) {
    uint32_t a;
    asm("{ .reg .u64 t; cvta.to.shared.u64 t, %1; cvt.u32.u64 %0, t; }" : "=r"(a) : "l"(p));
    return a;
}
// pack {lower=lo_val, upper=hi_val} as f16x2 (cvt: first src -> upper half)
__device__ __forceinline__ uint32_t packh(float lo_val, float hi_val) {
    uint32_t r;
    asm("cvt.rn.f16x2.f32 %0, %1, %2;" : "=r"(r) : "f"(hi_val), "f"(lo_val));
    return r;
}
__device__ __forceinline__ uint4 lds128(uint32_t a) {
    uint4 v;
    asm("ld.shared.v4.u32 {%0,%1,%2,%3}, [%4];"
        : "=r"(v.x), "=r"(v.y), "=r"(v.z), "=r"(v.w) : "r"(a));
    return v;
}
__device__ __forceinline__ float2 lds64f(uint32_t a) {
    float2 v;
    asm("ld.shared.v2.f32 {%0,%1}, [%2];" : "=f"(v.x), "=f"(v.y) : "r"(a));
    return v;
}
__device__ __forceinline__ void cpa16(uint32_t dst, const void* src) {
    asm volatile("cp.async.cg.shared.global [%0], [%1], 16;" :: "r"(dst), "l"(src) : "memory");
}
#define CP_COMMIT() asm volatile("cp.async.commit_group;" ::: "memory")
#define CP_WAIT0()  asm volatile("cp.async.wait_group 0;" ::: "memory")

__device__ __forceinline__ void hmma(float* d, const uint32_t* a, uint32_t b0, uint32_t b1) {
    asm("mma.sync.aligned.m16n8k16.row.col.f32.f16.f16.f32 "
        "{%0,%1,%2,%3}, {%4,%5,%6,%7}, {%8,%9}, {%0,%1,%2,%3};"
        : "+f"(d[0]), "+f"(d[1]), "+f"(d[2]), "+f"(d[3])
        : "r"(a[0]), "r"(a[1]), "r"(a[2]), "r"(a[3]), "r"(b0), "r"(b1));
}
// leaky via slct: (v >= 0) ? v : 0.01v  -- value-identical, 2 instr
__device__ __forceinline__ float leaky(float v) {
    float m = 0.01f * v, r;
    asm("slct.f32.f32 %0, %1, %2, %3;" : "=f"(r) : "f"(v), "f"(m), "f"(v));
    return r;
}

// ============================================================
// prep: fragment-permuted f16 weights, Wh/Wl interleaved:
//   uint4 @ (L*CHUNK + ((kf*NF+nf)*32 + lane)*16) =
//     { Wh(k,k+1), Wh(k+8,k+9), Wl(k,k+1), Wl(k+8,k+9) }
//   with n = nf*8 + lane/4, k = kf*16 + 2*(lane%4)
//   Wh = f16(w), Wl = f16(w - float(Wh))
// bias (float2 per (nf,q)) @ L*CHUNK + BIASOFF + (nf*4+q)*8
// ============================================================
#define NWT (NLAYERS * KF * NF * 32)
__global__ void prep(const float* __restrict__ W_in, const float* __restrict__ b_in,
                     const float* __restrict__ Ws, const float* __restrict__ bs,
                     const float* __restrict__ W_out) {
    int t = blockIdx.x * 256 + threadIdx.x;
    if (t < NWT) {
        int L = t / (KF * NF * 32);
        int r = t % (KF * NF * 32);
        int kf = r / (NF * 32);
        int r2 = r % (NF * 32);
        int nf = r2 / 32, lane = r2 % 32;
        int n = nf * 8 + (lane >> 2);
        int k = kf * 16 + 2 * (lane & 3);
        float v[4];  // (k, k+1, k+8, k+9)
#pragma unroll
        for (int e = 0; e < 4; e++) {
            int kk = k + (e & 1) + (e >> 1) * 8;
            float w = 0.0f;
            if (L == 0) {
                if (kk < 64 && n < 100) w = W_in[kk * 100 + n];
            } else {
                if (kk < 100 && n < 100) w = Ws[((size_t)(L - 1) * 100 + kk) * 100 + n];
            }
            v[e] = w;
        }
        __half h[4];
        float  l[4];
#pragma unroll
        for (int e = 0; e < 4; e++) {
            h[e] = __float2half_rn(v[e]);
            l[e] = v[e] - __half2float(h[e]);
        }
        __half2 hp0 = __halves2half2(h[0], h[1]);   // lo=v0, hi=v1
        __half2 hp1 = __halves2half2(h[2], h[3]);
        __half2 lp0 = __halves2half2(__float2half_rn(l[0]), __float2half_rn(l[1]));
        __half2 lp1 = __halves2half2(__float2half_rn(l[2]), __float2half_rn(l[3]));
        size_t off = (size_t)L * CHUNK + ((size_t)(kf * NF + nf) * 32 + lane) * 16;
        *(uint4*)(g_WP + off) = make_uint4(*(uint32_t*)&hp0, *(uint32_t*)&hp1,
                                           *(uint32_t*)&lp0, *(uint32_t*)&lp1);
        return;
    }
    t -= NWT;
    if (t < NLAYERS * NF * 4) {
        int m = t / (NF * 4);
        int r = t % (NF * 4);
        int nf = r / 4, q = r % 4;
        int c = nf * 8 + 2 * q;
        float b0 = (c < 100)     ? (m == 0 ? b_in[c]     : bs[(m - 1) * 100 + c])     : 0.0f;
        float b1 = (c + 1 < 100) ? (m == 0 ? b_in[c + 1] : bs[(m - 1) * 100 + c + 1]) : 0.0f;
        *(float2*)(g_WP + (size_t)m * CHUNK + BIASOFF + (size_t)r * 8) = make_float2(b0, b1);
        return;
    }
    t -= NLAYERS * NF * 4;
    if (t < NF * 4) {
        int nf = t / 4, q = t % 4;
        int c = nf * 8 + 2 * q;
        g_WOUTP[t] = make_float2(c < 100 ? W_out[c] : 0.0f,
                                 c + 1 < 100 ? W_out[c + 1] : 0.0f);
    }
}

// ============================================================
// main kernel: 256 threads (8 warps x 16 samples = 128/block)
// ============================================================
__global__ void __launch_bounds__(256, 2)
actor(const float* __restrict__ x, const float* __restrict__ b_out,
      float* __restrict__ out, int nsamples) {
    extern __shared__ unsigned char sm[];
    const uint32_t smb = smem_u32(sm);
    const int tid = threadIdx.x, lane = tid & 31, warp = tid >> 5;
    const int s0 = blockIdx.x * 128 + warp * 16;
    const int r = lane >> 2, kc = 2 * (lane & 3);
    const bool vlo = (s0 + r) < nsamples;
    const bool vhi = (s0 + r + 8) < nsamples;

    // ---- issue initial copies first (overlap with x-load) ----
    {
        const unsigned char* s0p = g_WP + tid * 16;
        const unsigned char* s1p = g_WP + CHUNK + tid * 16;
        uint32_t d0 = smb + tid * 16, d1 = smb + CHUNK + tid * 16;
#pragma unroll
        for (int i = 0; i < 12; i++) cpa16(d0 + i * 4096, s0p + (size_t)i * 4096);
#pragma unroll
        for (int i = 0; i < 12; i++) cpa16(d1 + i * 4096, s1p + (size_t)i * 4096);
        CP_COMMIT();
    }

    // ---- layer-0 A fragments (f16) straight from x (K=64 -> kf 0..3) ----
    uint32_t Ah[KF][4];
    {
        const float* xb = x + (size_t)s0 * 64;
#pragma unroll
        for (int kf = 0; kf < 4; kf++) {
            int k = kf * 16 + kc;
            float2 p00 = vlo ? *(const float2*)(xb + (size_t)r * 64 + k)           : make_float2(0.f, 0.f);
            float2 p01 = vlo ? *(const float2*)(xb + (size_t)r * 64 + k + 8)       : make_float2(0.f, 0.f);
            float2 p10 = vhi ? *(const float2*)(xb + (size_t)(r + 8) * 64 + k)     : make_float2(0.f, 0.f);
            float2 p11 = vhi ? *(const float2*)(xb + (size_t)(r + 8) * 64 + k + 8) : make_float2(0.f, 0.f);
            Ah[kf][0] = packh(p00.x, p00.y);
            Ah[kf][1] = packh(p10.x, p10.y);
            Ah[kf][2] = packh(p01.x, p01.y);
            Ah[kf][3] = packh(p11.x, p11.y);
        }
#pragma unroll
        for (int kf = 4; kf < KF; kf++) {
            Ah[kf][0] = Ah[kf][1] = Ah[kf][2] = Ah[kf][3] = 0u;
        }
    }

    // ---- anti-phase stagger: odd blocks delay ~half a layer ----
    if (blockIdx.x & 1) {
        unsigned long long t0 = clock64();
        while (clock64() - t0 < 4000ULL) { }
    }

    CP_WAIT0();
    __syncthreads();

    float po0 = 0.0f, po1 = 0.0f;  // head partials (rows r, r+8)

#pragma unroll 1
    for (int m = 0; m <= 100; m++) {
        const uint32_t bufA = smb + (uint32_t)(m & 1) * CHUNK;

        // D initialized to bias (from smem chunk)
        float D[NF][4];
        {
            uint32_t ba = bufA + BIASOFF + (uint32_t)(lane & 3) * 8;
#pragma unroll
            for (int nf = 0; nf < NF; nf++) {
                float2 bv = lds64f(ba + (uint32_t)nf * 32);
                D[nf][0] = bv.x; D[nf][1] = bv.y; D[nf][2] = bv.x; D[nf][3] = bv.y;
            }
        }

        // ---- 2-product f16 GEMM, nf-pair interleaved HMMA order ----
        // per-accumulator order: Wh then Wl per kf
#pragma unroll
        for (int kf = 0; kf < KF; kf++) {
            uint32_t ad = bufA + (uint32_t)(kf * NF) * 512 + lane * 16;
#pragma unroll
            for (int p = 0; p < 6; p++) {
                uint4 w0 = lds128(ad);
                uint4 w1 = lds128(ad + 512);
                float* D0 = D[2 * p];
                float* D1 = D[2 * p + 1];
                hmma(D0, Ah[kf], w0.x, w0.y);   // A * Wh
                hmma(D1, Ah[kf], w1.x, w1.y);
                hmma(D0, Ah[kf], w0.z, w0.w);   // A * Wl
                hmma(D1, Ah[kf], w1.z, w1.w);
                ad += 1024;
            }
            {   // nf = 12 (single)
                uint4 w0 = lds128(ad);
                hmma(D[12], Ah[kf], w0.x, w0.y);
                hmma(D[12], Ah[kf], w0.z, w0.w);
            }
        }

        // ---- epilogue (registers only): leaky + f16 requantize ----
        if (m < 100) {
#pragma unroll
            for (int nf = 0; nf < NF; nf++) {
                D[nf][0] = leaky(D[nf][0]);
                D[nf][1] = leaky(D[nf][1]);
                D[nf][2] = leaky(D[nf][2]);
                D[nf][3] = leaky(D[nf][3]);
            }
#pragma unroll
            for (int t2 = 0; t2 < 6; t2++) {
                const float* d0 = D[2 * t2];
                const float* d1 = D[2 * t2 + 1];
                Ah[t2][0] = packh(d0[0], d0[1]);
                Ah[t2][1] = packh(d0[2], d0[3]);
                Ah[t2][2] = packh(d1[0], d1[1]);
                Ah[t2][3] = packh(d1[2], d1[3]);
            }
            {   // t2 = 6: cols 96..103 from D[12]; 104..111 zero-pad
                const float* d0 = D[12];
                Ah[6][0] = packh(d0[0], d0[1]);
                Ah[6][1] = packh(d0[2], d0[3]);
                Ah[6][2] = 0u; Ah[6][3] = 0u;
            }
        } else {
            // head: h = leaky(layer-100 out), partial dot with W_out
#pragma unroll
            for (int nf = 0; nf < NF; nf++) {
                float2 w = g_WOUTP[nf * 4 + (lane & 3)];
                po0 += leaky(D[nf][0]) * w.x + leaky(D[nf][1]) * w.y;
                po1 += leaky(D[nf][2]) * w.x + leaky(D[nf][3]) * w.y;
            }
        }

        // ---- single barrier per layer ----
        CP_WAIT0();       // prior prefetch group (issued a full layer ago)
        __syncthreads();  // all GEMM reads of bufA done; prior copies visible

        if (m + 2 <= 100) {
            const unsigned char* sp = g_WP + (size_t)(m + 2) * CHUNK + tid * 16;
            uint32_t dp = bufA + tid * 16;
#pragma unroll
            for (int i = 0; i < 12; i++) cpa16(dp + i * 4096, sp + (size_t)i * 4096);
            CP_COMMIT();
        }
    }

    // ---- head reduce across the 4 lanes sharing a row ----
    po0 += __shfl_xor_sync(0xffffffff, po0, 1);
    po0 += __shfl_xor_sync(0xffffffff, po0, 2);
    po1 += __shfl_xor_sync(0xffffffff, po1, 1);
    po1 += __shfl_xor_sync(0xffffffff, po1, 2);
    if ((lane & 3) == 0) {
        float bo = b_out[0];
        if (vlo) out[s0 + r]     = tanhf(po0 + bo) * 4.5f + 5.5f;
        if (vhi) out[s0 + r + 8] = tanhf(po1 + bo) * 4.5f + 5.5f;
    }
}

extern "C" void kernel_launch(void* const* d_in, const int* in_sizes, int n_in,
                              void* d_out, int out_size) {
    const float* x     = (const float*)d_in[0];
    const float* W_in  = (const float*)d_in[1];
    const float* b_in  = (const float*)d_in[2];
    const float* Ws    = (const float*)d_in[3];
    const float* bs    = (const float*)d_in[4];
    const float* W_out = (const float*)d_in[5];
    const float* b_out = (const float*)d_in[6];
    float* out = (float*)d_out;

    int nsamples = in_sizes[0] / 64;
    int nblocks  = (nsamples + 127) / 128;

    const int PREP_TOTAL = NWT + NLAYERS * NF * 4 + NF * 4;
    prep<<<(PREP_TOTAL + 255) / 256, 256>>>(W_in, b_in, Ws, bs, W_out);

    size_t shmem = 2 * CHUNK;  // 98304
    cudaFuncSetAttribute(actor, cudaFuncAttributeMaxDynamicSharedMemorySize, (int)shmem);
    actor<<<nblocks, 256, shmem>>>(x, b_out, out, nsamples);
}

// round 11
// speedup vs baseline: 1.6693x; 1.0789x over previous
#include <cuda_runtime.h>
#include <cuda_fp16.h>
#include <cstdint>

// ============================================================
// Actor MLP via warp-level mma.sync, fp16 two-product scheme:
//   D = Af16 * Wh + Af16 * Wl   (Wh+Wl = W to ~22 bits)
// R11: M=32 per warp (two m16 row-groups share each weight
// fragment) -> halves shared-memory traffic per HMMA, which
// R10 profiling showed was the critical pipe. 256 threads,
// occupancy 1 (255 regs), 8 warps x 32 samples = 256/block.
// ============================================================

#define NF 13          // n-fragments (8 wide)  -> N = 104
#define KF 7           // k-fragments (16 wide) -> K = 112
#define CHUNK 49152    // per-layer chunk stride; weights 46592B + bias 416B
#define BIASOFF 46592  // bias offset inside chunk
#define NLAYERS 101    // layer 0 = W_in, layers 1..100 = hidden

__device__ __align__(16) unsigned char g_WP[NLAYERS * CHUNK];    // ~4.97 MB
__device__ __align__(16) float2 g_WOUTP[NF * 4];

// ---- helpers ----
__device__ __forceinline__ uint32_t smem_u32(const void* p) {
    uint32_t a;
    asm("{ .reg .u64 t; cvta.to.shared.u64 t, %1; cvt.u32.u64 %0, t; }" : "=r"(a) : "l"(p));
    return a;
}
// pack {lower=lo_val, upper=hi_val} as f16x2 (cvt: first src -> upper half)
__device__ __forceinline__ uint32_t packh(float lo_val, float hi_val) {
    uint32_t r;
    asm("cvt.rn.f16x2.f32 %0, %1, %2;" : "=r"(r) : "f"(hi_val), "f"(lo_val));
    return r;
}
__device__ __forceinline__ uint4 lds128(uint32_t a) {
    uint4 v;
    asm("ld.shared.v4.u32 {%0,%1,%2,%3}, [%4];"
        : "=r"(v.x), "=r"(v.y), "=r"(v.z), "=r"(v.w) : "r"(a));
    return v;
}
__device__ __forceinline__ float2 lds64f(uint32_t a) {
    float2 v;
    asm("ld.shared.v2.f32 {%0,%1}, [%2];" : "=f"(v.x), "=f"(v.y) : "r"(a));
    return v;
}
__device__ __forceinline__ void cpa16(uint32_t dst, const void* src) {
    asm volatile("cp.async.cg.shared.global [%0], [%1], 16;" :: "r"(dst), "l"(src) : "memory");
}
#define CP_COMMIT() asm volatile("cp.async.commit_group;" ::: "memory")
#define CP_WAIT0()  asm volatile("cp.async.wait_group 0;" ::: "memory")

__device__ __forceinline__ void hmma(float* d, const uint32_t* a, uint32_t b0, uint32_t b1) {
    asm("mma.sync.aligned.m16n8k16.row.col.f32.f16.f16.f32 "
        "{%0,%1,%2,%3}, {%4,%5,%6,%7}, {%8,%9}, {%0,%1,%2,%3};"
        : "+f"(d[0]), "+f"(d[1]), "+f"(d[2]), "+f"(d[3])
        : "r"(a[0]), "r"(a[1]), "r"(a[2]), "r"(a[3]), "r"(b0), "r"(b1));
}
// leaky via slct: (v >= 0) ? v : 0.01v  -- value-identical, 2 instr
__device__ __forceinline__ float leaky(float v) {
    float m = 0.01f * v, r;
    asm("slct.f32.f32 %0, %1, %2, %3;" : "=f"(r) : "f"(v), "f"(m), "f"(v));
    return r;
}

// ============================================================
// prep: fragment-permuted f16 weights, Wh/Wl interleaved:
//   uint4 @ (L*CHUNK + ((kf*NF+nf)*32 + lane)*16) =
//     { Wh(k,k+1), Wh(k+8,k+9), Wl(k,k+1), Wl(k+8,k+9) }
//   with n = nf*8 + lane/4, k = kf*16 + 2*(lane%4)
// bias (float2 per (nf,q)) @ L*CHUNK + BIASOFF + (nf*4+q)*8
// ============================================================
#define NWT (NLAYERS * KF * NF * 32)
__global__ void prep(const float* __restrict__ W_in, const float* __restrict__ b_in,
                     const float* __restrict__ Ws, const float* __restrict__ bs,
                     const float* __restrict__ W_out) {
    int t = blockIdx.x * 256 + threadIdx.x;
    if (t < NWT) {
        int L = t / (KF * NF * 32);
        int r = t % (KF * NF * 32);
        int kf = r / (NF * 32);
        int r2 = r % (NF * 32);
        int nf = r2 / 32, lane = r2 % 32;
        int n = nf * 8 + (lane >> 2);
        int k = kf * 16 + 2 * (lane & 3);
        float v[4];  // (k, k+1, k+8, k+9)
#pragma unroll
        for (int e = 0; e < 4; e++) {
            int kk = k + (e & 1) + (e >> 1) * 8;
            float w = 0.0f;
            if (L == 0) {
                if (kk < 64 && n < 100) w = W_in[kk * 100 + n];
            } else {
                if (kk < 100 && n < 100) w = Ws[((size_t)(L - 1) * 100 + kk) * 100 + n];
            }
            v[e] = w;
        }
        __half h[4];
        float  l[4];
#pragma unroll
        for (int e = 0; e < 4; e++) {
            h[e] = __float2half_rn(v[e]);
            l[e] = v[e] - __half2float(h[e]);
        }
        __half2 hp0 = __halves2half2(h[0], h[1]);
        __half2 hp1 = __halves2half2(h[2], h[3]);
        __half2 lp0 = __halves2half2(__float2half_rn(l[0]), __float2half_rn(l[1]));
        __half2 lp1 = __halves2half2(__float2half_rn(l[2]), __float2half_rn(l[3]));
        size_t off = (size_t)L * CHUNK + ((size_t)(kf * NF + nf) * 32 + lane) * 16;
        *(uint4*)(g_WP + off) = make_uint4(*(uint32_t*)&hp0, *(uint32_t*)&hp1,
                                           *(uint32_t*)&lp0, *(uint32_t*)&lp1);
        return;
    }
    t -= NWT;
    if (t < NLAYERS * NF * 4) {
        int m = t / (NF * 4);
        int r = t % (NF * 4);
        int nf = r / 4, q = r % 4;
        int c = nf * 8 + 2 * q;
        float b0 = (c < 100)     ? (m == 0 ? b_in[c]     : bs[(m - 1) * 100 + c])     : 0.0f;
        float b1 = (c + 1 < 100) ? (m == 0 ? b_in[c + 1] : bs[(m - 1) * 100 + c + 1]) : 0.0f;
        *(float2*)(g_WP + (size_t)m * CHUNK + BIASOFF + (size_t)r * 8) = make_float2(b0, b1);
        return;
    }
    t -= NLAYERS * NF * 4;
    if (t < NF * 4) {
        int nf = t / 4, q = t % 4;
        int c = nf * 8 + 2 * q;
        g_WOUTP[t] = make_float2(c < 100 ? W_out[c] : 0.0f,
                                 c + 1 < 100 ? W_out[c + 1] : 0.0f);
    }
}

// ============================================================
// main kernel: 256 threads, 8 warps x 32 samples = 256/block,
// occupancy 1 (255 regs available, 96KB smem)
// ============================================================
__global__ void __launch_bounds__(256, 1)
actor(const float* __restrict__ x, const float* __restrict__ b_out,
      float* __restrict__ out, int nsamples) {
    extern __shared__ unsigned char sm[];
    const uint32_t smb = smem_u32(sm);
    const int tid = threadIdx.x, lane = tid & 31, warp = tid >> 5;
    const int s0 = blockIdx.x * 256 + warp * 32;
    const int r = lane >> 2, kc = 2 * (lane & 3);
    const bool v0 = (s0 + r)      < nsamples;
    const bool v1 = (s0 + r + 8)  < nsamples;
    const bool v2 = (s0 + r + 16) < nsamples;
    const bool v3 = (s0 + r + 24) < nsamples;

    // ---- issue initial copies first (overlap with x-load) ----
    {
        const unsigned char* s0p = g_WP + tid * 16;
        const unsigned char* s1p = g_WP + CHUNK + tid * 16;
        uint32_t d0 = smb + tid * 16, d1 = smb + CHUNK + tid * 16;
#pragma unroll
        for (int i = 0; i < 12; i++) cpa16(d0 + i * 4096, s0p + (size_t)i * 4096);
#pragma unroll
        for (int i = 0; i < 12; i++) cpa16(d1 + i * 4096, s1p + (size_t)i * 4096);
        CP_COMMIT();
    }

    // ---- layer-0 A fragments (f16) straight from x (K=64 -> kf 0..3) ----
    uint32_t A0[KF][4], A1[KF][4];
    {
        const float* xb = x + (size_t)s0 * 64;
#pragma unroll
        for (int kf = 0; kf < 4; kf++) {
            int k = kf * 16 + kc;
            float2 pa0 = v0 ? *(const float2*)(xb + (size_t)r * 64 + k)            : make_float2(0.f, 0.f);
            float2 pa1 = v0 ? *(const float2*)(xb + (size_t)r * 64 + k + 8)        : make_float2(0.f, 0.f);
            float2 pb0 = v1 ? *(const float2*)(xb + (size_t)(r + 8) * 64 + k)      : make_float2(0.f, 0.f);
            float2 pb1 = v1 ? *(const float2*)(xb + (size_t)(r + 8) * 64 + k + 8)  : make_float2(0.f, 0.f);
            float2 pc0 = v2 ? *(const float2*)(xb + (size_t)(r + 16) * 64 + k)     : make_float2(0.f, 0.f);
            float2 pc1 = v2 ? *(const float2*)(xb + (size_t)(r + 16) * 64 + k + 8) : make_float2(0.f, 0.f);
            float2 pd0 = v3 ? *(const float2*)(xb + (size_t)(r + 24) * 64 + k)     : make_float2(0.f, 0.f);
            float2 pd1 = v3 ? *(const float2*)(xb + (size_t)(r + 24) * 64 + k + 8) : make_float2(0.f, 0.f);
            A0[kf][0] = packh(pa0.x, pa0.y);
            A0[kf][1] = packh(pb0.x, pb0.y);
            A0[kf][2] = packh(pa1.x, pa1.y);
            A0[kf][3] = packh(pb1.x, pb1.y);
            A1[kf][0] = packh(pc0.x, pc0.y);
            A1[kf][1] = packh(pd0.x, pd0.y);
            A1[kf][2] = packh(pc1.x, pc1.y);
            A1[kf][3] = packh(pd1.x, pd1.y);
        }
#pragma unroll
        for (int kf = 4; kf < KF; kf++) {
            A0[kf][0] = A0[kf][1] = A0[kf][2] = A0[kf][3] = 0u;
            A1[kf][0] = A1[kf][1] = A1[kf][2] = A1[kf][3] = 0u;
        }
    }

    CP_WAIT0();
    __syncthreads();

    float po0 = 0.0f, po1 = 0.0f, po2 = 0.0f, po3 = 0.0f;  // head partials

#pragma unroll 1
    for (int m = 0; m <= 100; m++) {
        const uint32_t bufA = smb + (uint32_t)(m & 1) * CHUNK;

        // D initialized to bias; [nf][0..3] = rows r/r+8, [nf][4..7] = rows r+16/r+24
        float D[NF][8];
        {
            uint32_t ba = bufA + BIASOFF + (uint32_t)(lane & 3) * 8;
#pragma unroll
            for (int nf = 0; nf < NF; nf++) {
                float2 bv = lds64f(ba + (uint32_t)nf * 32);
                D[nf][0] = bv.x; D[nf][1] = bv.y; D[nf][2] = bv.x; D[nf][3] = bv.y;
                D[nf][4] = bv.x; D[nf][5] = bv.y; D[nf][6] = bv.x; D[nf][7] = bv.y;
            }
        }

        // ---- 2-product f16 GEMM: 1 LDS.128 feeds 4 HMMAs ----
        // per-accumulator order: Wh then Wl per kf (identical to R10)
#pragma unroll
        for (int kf = 0; kf < KF; kf++) {
            uint32_t ad = bufA + (uint32_t)(kf * NF) * 512 + lane * 16;
#pragma unroll
            for (int nf = 0; nf < NF; nf++) {
                uint4 w = lds128(ad);
                hmma(&D[nf][0], A0[kf], w.x, w.y);   // A0 * Wh
                hmma(&D[nf][4], A1[kf], w.x, w.y);   // A1 * Wh
                hmma(&D[nf][0], A0[kf], w.z, w.w);   // A0 * Wl
                hmma(&D[nf][4], A1[kf], w.z, w.w);   // A1 * Wl
                ad += 512;
            }
        }

        // ---- epilogue (registers only): leaky + f16 requantize ----
        if (m < 100) {
#pragma unroll
            for (int nf = 0; nf < NF; nf++) {
#pragma unroll
                for (int e = 0; e < 8; e++) D[nf][e] = leaky(D[nf][e]);
            }
#pragma unroll
            for (int t2 = 0; t2 < 6; t2++) {
                const float* d0 = D[2 * t2];
                const float* d1 = D[2 * t2 + 1];
                A0[t2][0] = packh(d0[0], d0[1]);
                A0[t2][1] = packh(d0[2], d0[3]);
                A0[t2][2] = packh(d1[0], d1[1]);
                A0[t2][3] = packh(d1[2], d1[3]);
                A1[t2][0] = packh(d0[4], d0[5]);
                A1[t2][1] = packh(d0[6], d0[7]);
                A1[t2][2] = packh(d1[4], d1[5]);
                A1[t2][3] = packh(d1[6], d1[7]);
            }
            {   // t2 = 6: cols 96..103 from D[12]; 104..111 zero-pad
                const float* d0 = D[12];
                A0[6][0] = packh(d0[0], d0[1]);
                A0[6][1] = packh(d0[2], d0[3]);
                A0[6][2] = 0u; A0[6][3] = 0u;
                A1[6][0] = packh(d0[4], d0[5]);
                A1[6][1] = packh(d0[6], d0[7]);
                A1[6][2] = 0u; A1[6][3] = 0u;
            }
        } else {
            // head: h = leaky(layer-100 out), partial dot with W_out
#pragma unroll
            for (int nf = 0; nf < NF; nf++) {
                float2 w = g_WOUTP[nf * 4 + (lane & 3)];
                po0 += leaky(D[nf][0]) * w.x + leaky(D[nf][1]) * w.y;
                po1 += leaky(D[nf][2]) * w.x + leaky(D[nf][3]) * w.y;
                po2 += leaky(D[nf][4]) * w.x + leaky(D[nf][5]) * w.y;
                po3 += leaky(D[nf][6]) * w.x + leaky(D[nf][7]) * w.y;
            }
        }

        // ---- single barrier per layer ----
        CP_WAIT0();       // prior prefetch group (issued a full layer ago)
        __syncthreads();  // all GEMM reads of bufA done; prior copies visible

        if (m + 2 <= 100) {
            const unsigned char* sp = g_WP + (size_t)(m + 2) * CHUNK + tid * 16;
            uint32_t dp = bufA + tid * 16;
#pragma unroll
            for (int i = 0; i < 12; i++) cpa16(dp + i * 4096, sp + (size_t)i * 4096);
            CP_COMMIT();
        }
    }

    // ---- head reduce across the 4 lanes sharing a row ----
    po0 += __shfl_xor_sync(0xffffffff, po0, 1);
    po0 += __shfl_xor_sync(0xffffffff, po0, 2);
    po1 += __shfl_xor_sync(0xffffffff, po1, 1);
    po1 += __shfl_xor_sync(0xffffffff, po1, 2);
    po2 += __shfl_xor_sync(0xffffffff, po2, 1);
    po2 += __shfl_xor_sync(0xffffffff, po2, 2);
    po3 += __shfl_xor_sync(0xffffffff, po3, 1);
    po3 += __shfl_xor_sync(0xffffffff, po3, 2);
    if ((lane & 3) == 0) {
        float bo = b_out[0];
        if (v0) out[s0 + r]      = tanhf(po0 + bo) * 4.5f + 5.5f;
        if (v1) out[s0 + r + 8]  = tanhf(po1 + bo) * 4.5f + 5.5f;
        if (v2) out[s0 + r + 16] = tanhf(po2 + bo) * 4.5f + 5.5f;
        if (v3) out[s0 + r + 24] = tanhf(po3 + bo) * 4.5f + 5.5f;
    }
}

extern "C" void kernel_launch(void* const* d_in, const int* in_sizes, int n_in,
                              void* d_out, int out_size) {
    const float* x     = (const float*)d_in[0];
    const float* W_in  = (const float*)d_in[1];
    const float* b_in  = (const float*)d_in[2];
    const float* Ws    = (const float*)d_in[3];
    const float* bs    = (const float*)d_in[4];
    const float* W_out = (const float*)d_in[5];
    const float* b_out = (const float*)d_in[6];
    float* out = (float*)d_out;

    int nsamples = in_sizes[0] / 64;
    int nblocks  = (nsamples + 255) / 256;

    const int PREP_TOTAL = NWT + NLAYERS * NF * 4 + NF * 4;
    prep<<<(PREP_TOTAL + 255) / 256, 256>>>(W_in, b_in, Ws, bs, W_out);

    size_t shmem = 2 * CHUNK;  // 98304
    cudaFuncSetAttribute(actor, cudaFuncAttributeMaxDynamicSharedMemorySize, (int)shmem);
    actor<<<nblocks, 256, shmem>>>(x, b_out, out, nsamples);
}

// round 13
// speedup vs baseline: 1.7547x; 1.0512x over previous
#include <cuda_runtime.h>
#include <cuda_fp16.h>
#include <cstdint>

// ============================================================
// Actor MLP via warp-level mma.sync, fp16 two-product scheme:
//   D = Af16 * Wh + Af16 * Wl   (Wh+Wl = W to ~22 bits)
// R13: R11's exact math/layout, repartitioned into 128-thread
// blocks (4 warps x 32 samples) at occupancy 2. Independent
// block barriers let the two co-resident blocks drift out of
// phase, hiding each other's epilogue under GEMM.
// ============================================================

#define NF 13          // n-fragments (8 wide)  -> N = 104
#define KF 7           // k-fragments (16 wide) -> K = 112
#define CHUNK 49152    // per-layer chunk stride; weights 46592B + bias 416B
#define BIASOFF 46592  // bias offset inside chunk
#define NLAYERS 101    // layer 0 = W_in, layers 1..100 = hidden
#define NT 128         // threads per block (4 warps x 32 samples)
#define CPITER (CHUNK / (NT * 16))   // 24 cp.async iters per chunk

__device__ __align__(16) unsigned char g_WP[NLAYERS * CHUNK];    // ~4.97 MB
__device__ __align__(16) float2 g_WOUTP[NF * 4];

// ---- helpers ----
__device__ __forceinline__ uint32_t smem_u32(const void* p) {
    uint32_t a;
    asm("{ .reg .u64 t; cvta.to.shared.u64 t, %1; cvt.u32.u64 %0, t; }" : "=r"(a) : "l"(p));
    return a;
}
// pack {lower=lo_val, upper=hi_val} as f16x2 (cvt: first src -> upper half)
__device__ __forceinline__ uint32_t packh(float lo_val, float hi_val) {
    uint32_t r;
    asm("cvt.rn.f16x2.f32 %0, %1, %2;" : "=r"(r) : "f"(hi_val), "f"(lo_val));
    return r;
}
__device__ __forceinline__ uint4 lds128(uint32_t a) {
    uint4 v;
    asm("ld.shared.v4.u32 {%0,%1,%2,%3}, [%4];"
        : "=r"(v.x), "=r"(v.y), "=r"(v.z), "=r"(v.w) : "r"(a));
    return v;
}
__device__ __forceinline__ float2 lds64f(uint32_t a) {
    float2 v;
    asm("ld.shared.v2.f32 {%0,%1}, [%2];" : "=f"(v.x), "=f"(v.y) : "r"(a));
    return v;
}
__device__ __forceinline__ void cpa16(uint32_t dst, const void* src) {
    asm volatile("cp.async.cg.shared.global [%0], [%1], 16;" :: "r"(dst), "l"(src) : "memory");
}
#define CP_COMMIT() asm volatile("cp.async.commit_group;" ::: "memory")
#define CP_WAIT0()  asm volatile("cp.async.wait_group 0;" ::: "memory")

__device__ __forceinline__ void hmma(float* d, const uint32_t* a, uint32_t b0, uint32_t b1) {
    asm("mma.sync.aligned.m16n8k16.row.col.f32.f16.f16.f32 "
        "{%0,%1,%2,%3}, {%4,%5,%6,%7}, {%8,%9}, {%0,%1,%2,%3};"
        : "+f"(d[0]), "+f"(d[1]), "+f"(d[2]), "+f"(d[3])
        : "r"(a[0]), "r"(a[1]), "r"(a[2]), "r"(a[3]), "r"(b0), "r"(b1));
}
// leaky via slct: (v >= 0) ? v : 0.01v  -- value-identical, 2 instr
__device__ __forceinline__ float leaky(float v) {
    float m = 0.01f * v, r;
    asm("slct.f32.f32 %0, %1, %2, %3;" : "=f"(r) : "f"(v), "f"(m), "f"(v));
    return r;
}

// ============================================================
// prep: fragment-permuted f16 weights, Wh/Wl interleaved:
//   uint4 @ (L*CHUNK + ((kf*NF+nf)*32 + lane)*16) =
//     { Wh(k,k+1), Wh(k+8,k+9), Wl(k,k+1), Wl(k+8,k+9) }
//   with n = nf*8 + lane/4, k = kf*16 + 2*(lane%4)
// bias (float2 per (nf,q)) @ L*CHUNK + BIASOFF + (nf*4+q)*8
// ============================================================
#define NWT (NLAYERS * KF * NF * 32)
__global__ void prep(const float* __restrict__ W_in, const float* __restrict__ b_in,
                     const float* __restrict__ Ws, const float* __restrict__ bs,
                     const float* __restrict__ W_out) {
    int t = blockIdx.x * 256 + threadIdx.x;
    if (t < NWT) {
        int L = t / (KF * NF * 32);
        int r = t % (KF * NF * 32);
        int kf = r / (NF * 32);
        int r2 = r % (NF * 32);
        int nf = r2 / 32, lane = r2 % 32;
        int n = nf * 8 + (lane >> 2);
        int k = kf * 16 + 2 * (lane & 3);
        float v[4];  // (k, k+1, k+8, k+9)
#pragma unroll
        for (int e = 0; e < 4; e++) {
            int kk = k + (e & 1) + (e >> 1) * 8;
            float w = 0.0f;
            if (L == 0) {
                if (kk < 64 && n < 100) w = W_in[kk * 100 + n];
            } else {
                if (kk < 100 && n < 100) w = Ws[((size_t)(L - 1) * 100 + kk) * 100 + n];
            }
            v[e] = w;
        }
        __half h[4];
        float  l[4];
#pragma unroll
        for (int e = 0; e < 4; e++) {
            h[e] = __float2half_rn(v[e]);
            l[e] = v[e] - __half2float(h[e]);
        }
        __half2 hp0 = __halves2half2(h[0], h[1]);
        __half2 hp1 = __halves2half2(h[2], h[3]);
        __half2 lp0 = __halves2half2(__float2half_rn(l[0]), __float2half_rn(l[1]));
        __half2 lp1 = __halves2half2(__float2half_rn(l[2]), __float2half_rn(l[3]));
        size_t off = (size_t)L * CHUNK + ((size_t)(kf * NF + nf) * 32 + lane) * 16;
        *(uint4*)(g_WP + off) = make_uint4(*(uint32_t*)&hp0, *(uint32_t*)&hp1,
                                           *(uint32_t*)&lp0, *(uint32_t*)&lp1);
        return;
    }
    t -= NWT;
    if (t < NLAYERS * NF * 4) {
        int m = t / (NF * 4);
        int r = t % (NF * 4);
        int nf = r / 4, q = r % 4;
        int c = nf * 8 + 2 * q;
        float b0 = (c < 100)     ? (m == 0 ? b_in[c]     : bs[(m - 1) * 100 + c])     : 0.0f;
        float b1 = (c + 1 < 100) ? (m == 0 ? b_in[c + 1] : bs[(m - 1) * 100 + c + 1]) : 0.0f;
        *(float2*)(g_WP + (size_t)m * CHUNK + BIASOFF + (size_t)r * 8) = make_float2(b0, b1);
        return;
    }
    t -= NLAYERS * NF * 4;
    if (t < NF * 4) {
        int nf = t / 4, q = t % 4;
        int c = nf * 8 + 2 * q;
        g_WOUTP[t] = make_float2(c < 100 ? W_out[c] : 0.0f,
                                 c + 1 < 100 ? W_out[c + 1] : 0.0f);
    }
}

// ============================================================
// main kernel: 128 threads, 4 warps x 32 samples = 128/block,
// occupancy 2 (two independent blocks per SM)
// ============================================================
__global__ void __launch_bounds__(NT, 2)
actor(const float* __restrict__ x, const float* __restrict__ b_out,
      float* __restrict__ out, int nsamples) {
    extern __shared__ unsigned char sm[];
    const uint32_t smb = smem_u32(sm);
    const int tid = threadIdx.x, lane = tid & 31, warp = tid >> 5;
    const int s0 = blockIdx.x * NT + warp * 32;
    const int r = lane >> 2, kc = 2 * (lane & 3);
    const bool v0 = (s0 + r)      < nsamples;
    const bool v1 = (s0 + r + 8)  < nsamples;
    const bool v2 = (s0 + r + 16) < nsamples;
    const bool v3 = (s0 + r + 24) < nsamples;

    // ---- issue initial copies first (overlap with x-load) ----
    {
        const unsigned char* s0p = g_WP + tid * 16;
        const unsigned char* s1p = g_WP + CHUNK + tid * 16;
        uint32_t d0 = smb + tid * 16, d1 = smb + CHUNK + tid * 16;
#pragma unroll
        for (int i = 0; i < CPITER; i++) cpa16(d0 + i * (NT * 16), s0p + (size_t)i * (NT * 16));
#pragma unroll
        for (int i = 0; i < CPITER; i++) cpa16(d1 + i * (NT * 16), s1p + (size_t)i * (NT * 16));
        CP_COMMIT();
    }

    // ---- layer-0 A fragments (f16) straight from x (K=64 -> kf 0..3) ----
    uint32_t A0[KF][4], A1[KF][4];
    {
        const float* xb = x + (size_t)s0 * 64;
#pragma unroll
        for (int kf = 0; kf < 4; kf++) {
            int k = kf * 16 + kc;
            float2 pa0 = v0 ? *(const float2*)(xb + (size_t)r * 64 + k)            : make_float2(0.f, 0.f);
            float2 pa1 = v0 ? *(const float2*)(xb + (size_t)r * 64 + k + 8)        : make_float2(0.f, 0.f);
            float2 pb0 = v1 ? *(const float2*)(xb + (size_t)(r + 8) * 64 + k)      : make_float2(0.f, 0.f);
            float2 pb1 = v1 ? *(const float2*)(xb + (size_t)(r + 8) * 64 + k + 8)  : make_float2(0.f, 0.f);
            float2 pc0 = v2 ? *(const float2*)(xb + (size_t)(r + 16) * 64 + k)     : make_float2(0.f, 0.f);
            float2 pc1 = v2 ? *(const float2*)(xb + (size_t)(r + 16) * 64 + k + 8) : make_float2(0.f, 0.f);
            float2 pd0 = v3 ? *(const float2*)(xb + (size_t)(r + 24) * 64 + k)     : make_float2(0.f, 0.f);
            float2 pd1 = v3 ? *(const float2*)(xb + (size_t)(r + 24) * 64 + k + 8) : make_float2(0.f, 0.f);
            A0[kf][0] = packh(pa0.x, pa0.y);
            A0[kf][1] = packh(pb0.x, pb0.y);
            A0[kf][2] = packh(pa1.x, pa1.y);
            A0[kf][3] = packh(pb1.x, pb1.y);
            A1[kf][0] = packh(pc0.x, pc0.y);
            A1[kf][1] = packh(pd0.x, pd0.y);
            A1[kf][2] = packh(pc1.x, pc1.y);
            A1[kf][3] = packh(pd1.x, pd1.y);
        }
#pragma unroll
        for (int kf = 4; kf < KF; kf++) {
            A0[kf][0] = A0[kf][1] = A0[kf][2] = A0[kf][3] = 0u;
            A1[kf][0] = A1[kf][1] = A1[kf][2] = A1[kf][3] = 0u;
        }
    }

    CP_WAIT0();
    __syncthreads();

    float po0 = 0.0f, po1 = 0.0f, po2 = 0.0f, po3 = 0.0f;  // head partials

#pragma unroll 1
    for (int m = 0; m <= 100; m++) {
        const uint32_t bufA = smb + (uint32_t)(m & 1) * CHUNK;

        // D initialized to bias; [nf][0..3] = rows r/r+8, [nf][4..7] = rows r+16/r+24
        float D[NF][8];
        {
            uint32_t ba = bufA + BIASOFF + (uint32_t)(lane & 3) * 8;
#pragma unroll
            for (int nf = 0; nf < NF; nf++) {
                float2 bv = lds64f(ba + (uint32_t)nf * 32);
                D[nf][0] = bv.x; D[nf][1] = bv.y; D[nf][2] = bv.x; D[nf][3] = bv.y;
                D[nf][4] = bv.x; D[nf][5] = bv.y; D[nf][6] = bv.x; D[nf][7] = bv.y;
            }
        }

        // ---- 2-product f16 GEMM: 1 LDS.128 feeds 4 HMMAs ----
        // per-accumulator order: Wh then Wl per kf (identical to R11)
#pragma unroll
        for (int kf = 0; kf < KF; kf++) {
            uint32_t ad = bufA + (uint32_t)(kf * NF) * 512 + lane * 16;
#pragma unroll
            for (int nf = 0; nf < NF; nf++) {
                uint4 w = lds128(ad);
                hmma(&D[nf][0], A0[kf], w.x, w.y);   // A0 * Wh
                hmma(&D[nf][4], A1[kf], w.x, w.y);   // A1 * Wh
                hmma(&D[nf][0], A0[kf], w.z, w.w);   // A0 * Wl
                hmma(&D[nf][4], A1[kf], w.z, w.w);   // A1 * Wl
                ad += 512;
            }
        }

        // ---- epilogue (registers only): leaky + f16 requantize ----
        if (m < 100) {
#pragma unroll
            for (int nf = 0; nf < NF; nf++) {
#pragma unroll
                for (int e = 0; e < 8; e++) D[nf][e] = leaky(D[nf][e]);
            }
#pragma unroll
            for (int t2 = 0; t2 < 6; t2++) {
                const float* d0 = D[2 * t2];
                const float* d1 = D[2 * t2 + 1];
                A0[t2][0] = packh(d0[0], d0[1]);
                A0[t2][1] = packh(d0[2], d0[3]);
                A0[t2][2] = packh(d1[0], d1[1]);
                A0[t2][3] = packh(d1[2], d1[3]);
                A1[t2][0] = packh(d0[4], d0[5]);
                A1[t2][1] = packh(d0[6], d0[7]);
                A1[t2][2] = packh(d1[4], d1[5]);
                A1[t2][3] = packh(d1[6], d1[7]);
            }
            {   // t2 = 6: cols 96..103 from D[12]; 104..111 zero-pad
                const float* d0 = D[12];
                A0[6][0] = packh(d0[0], d0[1]);
                A0[6][1] = packh(d0[2], d0[3]);
                A0[6][2] = 0u; A0[6][3] = 0u;
                A1[6][0] = packh(d0[4], d0[5]);
                A1[6][1] = packh(d0[6], d0[7]);
                A1[6][2] = 0u; A1[6][3] = 0u;
            }
        } else {
            // head: h = leaky(layer-100 out), partial dot with W_out
#pragma unroll
            for (int nf = 0; nf < NF; nf++) {
                float2 w = g_WOUTP[nf * 4 + (lane & 3)];
                po0 += leaky(D[nf][0]) * w.x + leaky(D[nf][1]) * w.y;
                po1 += leaky(D[nf][2]) * w.x + leaky(D[nf][3]) * w.y;
                po2 += leaky(D[nf][4]) * w.x + leaky(D[nf][5]) * w.y;
                po3 += leaky(D[nf][6]) * w.x + leaky(D[nf][7]) * w.y;
            }
        }

        // ---- single barrier per layer ----
        CP_WAIT0();       // prior prefetch group (issued a full layer ago)
        __syncthreads();  // all GEMM reads of bufA done; prior copies visible

        if (m + 2 <= 100) {
            const unsigned char* sp = g_WP + (size_t)(m + 2) * CHUNK + tid * 16;
            uint32_t dp = bufA + tid * 16;
#pragma unroll
            for (int i = 0; i < CPITER; i++) cpa16(dp + i * (NT * 16), sp + (size_t)i * (NT * 16));
            CP_COMMIT();
        }
    }

    // ---- head reduce across the 4 lanes sharing a row ----
    po0 += __shfl_xor_sync(0xffffffff, po0, 1);
    po0 += __shfl_xor_sync(0xffffffff, po0, 2);
    po1 += __shfl_xor_sync(0xffffffff, po1, 1);
    po1 += __shfl_xor_sync(0xffffffff, po1, 2);
    po2 += __shfl_xor_sync(0xffffffff, po2, 1);
    po2 += __shfl_xor_sync(0xffffffff, po2, 2);
    po3 += __shfl_xor_sync(0xffffffff, po3, 1);
    po3 += __shfl_xor_sync(0xffffffff, po3, 2);
    if ((lane & 3) == 0) {
        float bo = b_out[0];
        if (v0) out[s0 + r]      = tanhf(po0 + bo) * 4.5f + 5.5f;
        if (v1) out[s0 + r + 8]  = tanhf(po1 + bo) * 4.5f + 5.5f;
        if (v2) out[s0 + r + 16] = tanhf(po2 + bo) * 4.5f + 5.5f;
        if (v3) out[s0 + r + 24] = tanhf(po3 + bo) * 4.5f + 5.5f;
    }
}

extern "C" void kernel_launch(void* const* d_in, const int* in_sizes, int n_in,
                              void* d_out, int out_size) {
    const float* x     = (const float*)d_in[0];
    const float* W_in  = (const float*)d_in[1];
    const float* b_in  = (const float*)d_in[2];
    const float* Ws    = (const float*)d_in[3];
    const float* bs    = (const float*)d_in[4];
    const float* W_out = (const float*)d_in[5];
    const float* b_out = (const float*)d_in[6];
    float* out = (float*)d_out;

    int nsamples = in_sizes[0] / 64;
    int nblocks  = (nsamples + NT - 1) / NT;

    const int PREP_TOTAL = NWT + NLAYERS * NF * 4 + NF * 4;
    prep<<<(PREP_TOTAL + 255) / 256, 256>>>(W_in, b_in, Ws, bs, W_out);

    size_t shmem = 2 * CHUNK;  // 98304
    cudaFuncSetAttribute(actor, cudaFuncAttributeMaxDynamicSharedMemorySize, (int)shmem);
    actor<<<nblocks, NT, shmem>>>(x, b_out, out, nsamples);
}

// round 14
// speedup vs baseline: 2.9738x; 1.6948x over previous
#include <cuda_runtime.h>
#include <cuda_fp16.h>
#include <cstdint>

// ============================================================
// Actor MLP via warp-level mma.sync, SINGLE-product f16 GEMM:
//   D = Af16 * Wf16      (both quantized to f16, fp32 accum)
// Error model: A-quant (2^-11/layer) and W-quant (2^-11/layer)
// are independent random walks -> ~sqrt(2) * 4.74e-4 ~= 6.7e-4,
// under the 1e-3 gate. Halves HMMA count and smem traffic vs
// the two-product R13. 128-thread blocks (4 warps x 32 samples),
// occupancy 2, independent block barriers.
// ============================================================

#define NF 13          // n-fragments (8 wide)  -> N = 104
#define KF 7           // k-fragments (16 wide) -> K = 112
#define CHUNK 24576    // per-layer chunk stride; weights 23296B + bias 416B
#define BIASOFF 23296  // bias offset inside chunk
#define NLAYERS 101    // layer 0 = W_in, layers 1..100 = hidden
#define NT 128         // threads per block (4 warps x 32 samples)
#define CPITER (CHUNK / (NT * 16))   // 12 cp.async iters per chunk

__device__ __align__(16) unsigned char g_WP[NLAYERS * CHUNK];    // ~2.48 MB
__device__ __align__(16) float2 g_WOUTP[NF * 4];

// ---- helpers ----
__device__ __forceinline__ uint32_t smem_u32(const void* p) {
    uint32_t a;
    asm("{ .reg .u64 t; cvta.to.shared.u64 t, %1; cvt.u32.u64 %0, t; }" : "=r"(a) : "l"(p));
    return a;
}
// pack {lower=lo_val, upper=hi_val} as f16x2 (cvt: first src -> upper half)
__device__ __forceinline__ uint32_t packh(float lo_val, float hi_val) {
    uint32_t r;
    asm("cvt.rn.f16x2.f32 %0, %1, %2;" : "=r"(r) : "f"(hi_val), "f"(lo_val));
    return r;
}
__device__ __forceinline__ uint2 lds64u(uint32_t a) {
    uint2 v;
    asm("ld.shared.v2.u32 {%0,%1}, [%2];" : "=r"(v.x), "=r"(v.y) : "r"(a));
    return v;
}
__device__ __forceinline__ float2 lds64f(uint32_t a) {
    float2 v;
    asm("ld.shared.v2.f32 {%0,%1}, [%2];" : "=f"(v.x), "=f"(v.y) : "r"(a));
    return v;
}
__device__ __forceinline__ void cpa16(uint32_t dst, const void* src) {
    asm volatile("cp.async.cg.shared.global [%0], [%1], 16;" :: "r"(dst), "l"(src) : "memory");
}
#define CP_COMMIT() asm volatile("cp.async.commit_group;" ::: "memory")
#define CP_WAIT0()  asm volatile("cp.async.wait_group 0;" ::: "memory")

__device__ __forceinline__ void hmma(float* d, const uint32_t* a, uint32_t b0, uint32_t b1) {
    asm("mma.sync.aligned.m16n8k16.row.col.f32.f16.f16.f32 "
        "{%0,%1,%2,%3}, {%4,%5,%6,%7}, {%8,%9}, {%0,%1,%2,%3};"
        : "+f"(d[0]), "+f"(d[1]), "+f"(d[2]), "+f"(d[3])
        : "r"(a[0]), "r"(a[1]), "r"(a[2]), "r"(a[3]), "r"(b0), "r"(b1));
}
// leaky via slct: (v >= 0) ? v : 0.01v  -- value-identical, 2 instr
__device__ __forceinline__ float leaky(float v) {
    float m = 0.01f * v, r;
    asm("slct.f32.f32 %0, %1, %2, %3;" : "=f"(r) : "f"(v), "f"(m), "f"(v));
    return r;
}

// ============================================================
// prep: fragment-permuted f16 weights (single plane):
//   uint2 @ (L*CHUNK + ((kf*NF+nf)*32 + lane)*8) =
//     { W(k,k+1), W(k+8,k+9) }   all f16(w)
//   with n = nf*8 + lane/4, k = kf*16 + 2*(lane%4)
// bias (float2 per (nf,q)) @ L*CHUNK + BIASOFF + (nf*4+q)*8
// ============================================================
#define NWT (NLAYERS * KF * NF * 32)
__global__ void prep(const float* __restrict__ W_in, const float* __restrict__ b_in,
                     const float* __restrict__ Ws, const float* __restrict__ bs,
                     const float* __restrict__ W_out) {
    int t = blockIdx.x * 256 + threadIdx.x;
    if (t < NWT) {
        int L = t / (KF * NF * 32);
        int r = t % (KF * NF * 32);
        int kf = r / (NF * 32);
        int r2 = r % (NF * 32);
        int nf = r2 / 32, lane = r2 % 32;
        int n = nf * 8 + (lane >> 2);
        int k = kf * 16 + 2 * (lane & 3);
        float v[4];  // (k, k+1, k+8, k+9)
#pragma unroll
        for (int e = 0; e < 4; e++) {
            int kk = k + (e & 1) + (e >> 1) * 8;
            float w = 0.0f;
            if (L == 0) {
                if (kk < 64 && n < 100) w = W_in[kk * 100 + n];
            } else {
                if (kk < 100 && n < 100) w = Ws[((size_t)(L - 1) * 100 + kk) * 100 + n];
            }
            v[e] = w;
        }
        __half2 hp0 = __halves2half2(__float2half_rn(v[0]), __float2half_rn(v[1]));
        __half2 hp1 = __halves2half2(__float2half_rn(v[2]), __float2half_rn(v[3]));
        size_t off = (size_t)L * CHUNK + ((size_t)(kf * NF + nf) * 32 + lane) * 8;
        *(uint2*)(g_WP + off) = make_uint2(*(uint32_t*)&hp0, *(uint32_t*)&hp1);
        return;
    }
    t -= NWT;
    if (t < NLAYERS * NF * 4) {
        int m = t / (NF * 4);
        int r = t % (NF * 4);
        int nf = r / 4, q = r % 4;
        int c = nf * 8 + 2 * q;
        float b0 = (c < 100)     ? (m == 0 ? b_in[c]     : bs[(m - 1) * 100 + c])     : 0.0f;
        float b1 = (c + 1 < 100) ? (m == 0 ? b_in[c + 1] : bs[(m - 1) * 100 + c + 1]) : 0.0f;
        *(float2*)(g_WP + (size_t)m * CHUNK + BIASOFF + (size_t)r * 8) = make_float2(b0, b1);
        return;
    }
    t -= NLAYERS * NF * 4;
    if (t < NF * 4) {
        int nf = t / 4, q = t % 4;
        int c = nf * 8 + 2 * q;
        g_WOUTP[t] = make_float2(c < 100 ? W_out[c] : 0.0f,
                                 c + 1 < 100 ? W_out[c + 1] : 0.0f);
    }
}

// ============================================================
// main kernel: 128 threads, 4 warps x 32 samples = 128/block,
// occupancy 2 (two independent blocks per SM)
// ============================================================
__global__ void __launch_bounds__(NT, 2)
actor(const float* __restrict__ x, const float* __restrict__ b_out,
      float* __restrict__ out, int nsamples) {
    extern __shared__ unsigned char sm[];
    const uint32_t smb = smem_u32(sm);
    const int tid = threadIdx.x, lane = tid & 31, warp = tid >> 5;
    const int s0 = blockIdx.x * NT + warp * 32;
    const int r = lane >> 2, kc = 2 * (lane & 3);
    const bool v0 = (s0 + r)      < nsamples;
    const bool v1 = (s0 + r + 8)  < nsamples;
    const bool v2 = (s0 + r + 16) < nsamples;
    const bool v3 = (s0 + r + 24) < nsamples;

    // ---- issue initial copies first (overlap with x-load) ----
    {
        const unsigned char* s0p = g_WP + tid * 16;
        const unsigned char* s1p = g_WP + CHUNK + tid * 16;
        uint32_t d0 = smb + tid * 16, d1 = smb + CHUNK + tid * 16;
#pragma unroll
        for (int i = 0; i < CPITER; i++) cpa16(d0 + i * (NT * 16), s0p + (size_t)i * (NT * 16));
#pragma unroll
        for (int i = 0; i < CPITER; i++) cpa16(d1 + i * (NT * 16), s1p + (size_t)i * (NT * 16));
        CP_COMMIT();
    }

    // ---- layer-0 A fragments (f16) straight from x (K=64 -> kf 0..3) ----
    uint32_t A0[KF][4], A1[KF][4];
    {
        const float* xb = x + (size_t)s0 * 64;
#pragma unroll
        for (int kf = 0; kf < 4; kf++) {
            int k = kf * 16 + kc;
            float2 pa0 = v0 ? *(const float2*)(xb + (size_t)r * 64 + k)            : make_float2(0.f, 0.f);
            float2 pa1 = v0 ? *(const float2*)(xb + (size_t)r * 64 + k + 8)        : make_float2(0.f, 0.f);
            float2 pb0 = v1 ? *(const float2*)(xb + (size_t)(r + 8) * 64 + k)      : make_float2(0.f, 0.f);
            float2 pb1 = v1 ? *(const float2*)(xb + (size_t)(r + 8) * 64 + k + 8)  : make_float2(0.f, 0.f);
            float2 pc0 = v2 ? *(const float2*)(xb + (size_t)(r + 16) * 64 + k)     : make_float2(0.f, 0.f);
            float2 pc1 = v2 ? *(const float2*)(xb + (size_t)(r + 16) * 64 + k + 8) : make_float2(0.f, 0.f);
            float2 pd0 = v3 ? *(const float2*)(xb + (size_t)(r + 24) * 64 + k)     : make_float2(0.f, 0.f);
            float2 pd1 = v3 ? *(const float2*)(xb + (size_t)(r + 24) * 64 + k + 8) : make_float2(0.f, 0.f);
            A0[kf][0] = packh(pa0.x, pa0.y);
            A0[kf][1] = packh(pb0.x, pb0.y);
            A0[kf][2] = packh(pa1.x, pa1.y);
            A0[kf][3] = packh(pb1.x, pb1.y);
            A1[kf][0] = packh(pc0.x, pc0.y);
            A1[kf][1] = packh(pd0.x, pd0.y);
            A1[kf][2] = packh(pc1.x, pc1.y);
            A1[kf][3] = packh(pd1.x, pd1.y);
        }
#pragma unroll
        for (int kf = 4; kf < KF; kf++) {
            A0[kf][0] = A0[kf][1] = A0[kf][2] = A0[kf][3] = 0u;
            A1[kf][0] = A1[kf][1] = A1[kf][2] = A1[kf][3] = 0u;
        }
    }

    CP_WAIT0();
    __syncthreads();

    float po0 = 0.0f, po1 = 0.0f, po2 = 0.0f, po3 = 0.0f;  // head partials

#pragma unroll 1
    for (int m = 0; m <= 100; m++) {
        const uint32_t bufA = smb + (uint32_t)(m & 1) * CHUNK;

        // D initialized to bias; [nf][0..3] = rows r/r+8, [nf][4..7] = rows r+16/r+24
        float D[NF][8];
        {
            uint32_t ba = bufA + BIASOFF + (uint32_t)(lane & 3) * 8;
#pragma unroll
            for (int nf = 0; nf < NF; nf++) {
                float2 bv = lds64f(ba + (uint32_t)nf * 32);
                D[nf][0] = bv.x; D[nf][1] = bv.y; D[nf][2] = bv.x; D[nf][3] = bv.y;
                D[nf][4] = bv.x; D[nf][5] = bv.y; D[nf][6] = bv.x; D[nf][7] = bv.y;
            }
        }

        // ---- single-product f16 GEMM: 1 LDS.64 feeds 2 HMMAs ----
#pragma unroll
        for (int kf = 0; kf < KF; kf++) {
            uint32_t ad = bufA + (uint32_t)(kf * NF) * 256 + lane * 8;
#pragma unroll
            for (int nf = 0; nf < NF; nf++) {
                uint2 w = lds64u(ad);
                hmma(&D[nf][0], A0[kf], w.x, w.y);   // A0 * W
                hmma(&D[nf][4], A1[kf], w.x, w.y);   // A1 * W
                ad += 256;
            }
        }

        // ---- epilogue (registers only): leaky + f16 requantize ----
        if (m < 100) {
#pragma unroll
            for (int nf = 0; nf < NF; nf++) {
#pragma unroll
                for (int e = 0; e < 8; e++) D[nf][e] = leaky(D[nf][e]);
            }
#pragma unroll
            for (int t2 = 0; t2 < 6; t2++) {
                const float* d0 = D[2 * t2];
                const float* d1 = D[2 * t2 + 1];
                A0[t2][0] = packh(d0[0], d0[1]);
                A0[t2][1] = packh(d0[2], d0[3]);
                A0[t2][2] = packh(d1[0], d1[1]);
                A0[t2][3] = packh(d1[2], d1[3]);
                A1[t2][0] = packh(d0[4], d0[5]);
                A1[t2][1] = packh(d0[6], d0[7]);
                A1[t2][2] = packh(d1[4], d1[5]);
                A1[t2][3] = packh(d1[6], d1[7]);
            }
            {   // t2 = 6: cols 96..103 from D[12]; 104..111 zero-pad
                const float* d0 = D[12];
                A0[6][0] = packh(d0[0], d0[1]);
                A0[6][1] = packh(d0[2], d0[3]);
                A0[6][2] = 0u; A0[6][3] = 0u;
                A1[6][0] = packh(d0[4], d0[5]);
                A1[6][1] = packh(d0[6], d0[7]);
                A1[6][2] = 0u; A1[6][3] = 0u;
            }
        } else {
            // head: h = leaky(layer-100 out), partial dot with W_out
#pragma unroll
            for (int nf = 0; nf < NF; nf++) {
                float2 w = g_WOUTP[nf * 4 + (lane & 3)];
                po0 += leaky(D[nf][0]) * w.x + leaky(D[nf][1]) * w.y;
                po1 += leaky(D[nf][2]) * w.x + leaky(D[nf][3]) * w.y;
                po2 += leaky(D[nf][4]) * w.x + leaky(D[nf][5]) * w.y;
                po3 += leaky(D[nf][6]) * w.x + leaky(D[nf][7]) * w.y;
            }
        }

        // ---- single barrier per layer ----
        CP_WAIT0();       // prior prefetch group (issued a full layer ago)
        __syncthreads();  // all GEMM reads of bufA done; prior copies visible

        if (m + 2 <= 100) {
            const unsigned char* sp = g_WP + (size_t)(m + 2) * CHUNK + tid * 16;
            uint32_t dp = bufA + tid * 16;
#pragma unroll
            for (int i = 0; i < CPITER; i++) cpa16(dp + i * (NT * 16), sp + (size_t)i * (NT * 16));
            CP_COMMIT();
        }
    }

    // ---- head reduce across the 4 lanes sharing a row ----
    po0 += __shfl_xor_sync(0xffffffff, po0, 1);
    po0 += __shfl_xor_sync(0xffffffff, po0, 2);
    po1 += __shfl_xor_sync(0xffffffff, po1, 1);
    po1 += __shfl_xor_sync(0xffffffff, po1, 2);
    po2 += __shfl_xor_sync(0xffffffff, po2, 1);
    po2 += __shfl_xor_sync(0xffffffff, po2, 2);
    po3 += __shfl_xor_sync(0xffffffff, po3, 1);
    po3 += __shfl_xor_sync(0xffffffff, po3, 2);
    if ((lane & 3) == 0) {
        float bo = b_out[0];
        if (v0) out[s0 + r]      = tanhf(po0 + bo) * 4.5f + 5.5f;
        if (v1) out[s0 + r + 8]  = tanhf(po1 + bo) * 4.5f + 5.5f;
        if (v2) out[s0 + r + 16] = tanhf(po2 + bo) * 4.5f + 5.5f;
        if (v3) out[s0 + r + 24] = tanhf(po3 + bo) * 4.5f + 5.5f;
    }
}

extern "C" void kernel_launch(void* const* d_in, const int* in_sizes, int n_in,
                              void* d_out, int out_size) {
    const float* x     = (const float*)d_in[0];
    const float* W_in  = (const float*)d_in[1];
    const float* b_in  = (const float*)d_in[2];
    const float* Ws    = (const float*)d_in[3];
    const float* bs    = (const float*)d_in[4];
    const float* W_out = (const float*)d_in[5];
    const float* b_out = (const float*)d_in[6];
    float* out = (float*)d_out;

    int nsamples = in_sizes[0] / 64;
    int nblocks  = (nsamples + NT - 1) / NT;

    const int PREP_TOTAL = NWT + NLAYERS * NF * 4 + NF * 4;
    prep<<<(PREP_TOTAL + 255) / 256, 256>>>(W_in, b_in, Ws, bs, W_out);

    size_t shmem = 2 * CHUNK;  // 49152
    cudaFuncSetAttribute(actor, cudaFuncAttributeMaxDynamicSharedMemorySize, (int)shmem);
    actor<<<nblocks, NT, shmem>>>(x, b_out, out, nsamples);
}

// round 15
// speedup vs baseline: 3.0058x; 1.0108x over previous
#include <cuda_runtime.h>
#include <cuda_fp16.h>
#include <cstdint>

// ============================================================
// Actor MLP via warp-level mma.sync, single-product f16 GEMM:
//   D = Af16 * Wf16   (fp32 accum)
// R15: mbarrier-decoupled TRIPLE weight buffering. No
// __syncthreads in the layer loop: per-buffer full/free
// mbarriers let warps drift ~1 layer apart so each warp's
// epilogue overlaps other warps' HMMAs. GEMM/epilogue math is
// byte-identical to R14 (rel_err must stay 6.153473e-4).
// 128-thread blocks (4 warps x 32 samples), occupancy 2.
// ============================================================

#define NF 13          // n-fragments (8 wide)  -> N = 104
#define KF 7           // k-fragments (16 wide) -> K = 112
#define CHUNK 24576    // per-layer chunk stride; weights 23296B + bias 416B
#define BIASOFF 23296  // bias offset inside chunk
#define NLAYERS 101    // layer 0 = W_in, layers 1..100 = hidden
#define NT 128         // threads per block (4 warps x 32 samples)
#define NBUF 3
#define CPITER (CHUNK / (NT * 16))   // 12 cp.async iters per chunk per thread
#define MBOFF (NBUF * CHUNK)         // mbarrier region: full[3] then free[3]
#define SMTOT (MBOFF + 64)

__device__ __align__(16) unsigned char g_WP[NLAYERS * CHUNK];    // ~2.48 MB
__device__ __align__(16) float2 g_WOUTP[NF * 4];

// ---- helpers ----
__device__ __forceinline__ uint32_t smem_u32(const void* p) {
    uint32_t a;
    asm("{ .reg .u64 t; cvta.to.shared.u64 t, %1; cvt.u32.u64 %0, t; }" : "=r"(a) : "l"(p));
    return a;
}
// pack {lower=lo_val, upper=hi_val} as f16x2 (cvt: first src -> upper half)
__device__ __forceinline__ uint32_t packh(float lo_val, float hi_val) {
    uint32_t r;
    asm("cvt.rn.f16x2.f32 %0, %1, %2;" : "=r"(r) : "f"(hi_val), "f"(lo_val));
    return r;
}
__device__ __forceinline__ uint2 lds64u(uint32_t a) {
    uint2 v;
    asm("ld.shared.v2.u32 {%0,%1}, [%2];" : "=r"(v.x), "=r"(v.y) : "r"(a));
    return v;
}
__device__ __forceinline__ float2 lds64f(uint32_t a) {
    float2 v;
    asm("ld.shared.v2.f32 {%0,%1}, [%2];" : "=f"(v.x), "=f"(v.y) : "r"(a));
    return v;
}
__device__ __forceinline__ void cpa16(uint32_t dst, const void* src) {
    asm volatile("cp.async.cg.shared.global [%0], [%1], 16;" :: "r"(dst), "l"(src) : "memory");
}
// ---- mbarrier primitives (sm_80/90 baseline, no 'a' features) ----
__device__ __forceinline__ void mbar_init(uint32_t a, uint32_t cnt) {
    asm volatile("mbarrier.init.shared.b64 [%0], %1;" :: "r"(a), "r"(cnt) : "memory");
}
__device__ __forceinline__ void mbar_arrive(uint32_t a) {
    unsigned long long st;
    asm volatile("mbarrier.arrive.shared.b64 %0, [%1];" : "=l"(st) : "r"(a) : "memory");
}
__device__ __forceinline__ void mbar_wait(uint32_t a, uint32_t par) {
    asm volatile(
        "{\n\t.reg .pred P;\n\t"
        "WL%=:\n\t"
        "mbarrier.try_wait.parity.shared.b64 P, [%0], %1, 0x989680;\n\t"
        "@!P bra WL%=;\n\t}"
        :: "r"(a), "r"(par) : "memory");
}
// one arrival on [a] when all prior cp.async of this thread complete
__device__ __forceinline__ void cp_mbar_arrive(uint32_t a) {
    asm volatile("cp.async.mbarrier.arrive.noinc.shared.b64 [%0];" :: "r"(a) : "memory");
}

__device__ __forceinline__ void hmma(float* d, const uint32_t* a, uint32_t b0, uint32_t b1) {
    asm("mma.sync.aligned.m16n8k16.row.col.f32.f16.f16.f32 "
        "{%0,%1,%2,%3}, {%4,%5,%6,%7}, {%8,%9}, {%0,%1,%2,%3};"
        : "+f"(d[0]), "+f"(d[1]), "+f"(d[2]), "+f"(d[3])
        : "r"(a[0]), "r"(a[1]), "r"(a[2]), "r"(a[3]), "r"(b0), "r"(b1));
}
// leaky via slct: (v >= 0) ? v : 0.01v  -- value-identical, 2 instr
__device__ __forceinline__ float leaky(float v) {
    float m = 0.01f * v, r;
    asm("slct.f32.f32 %0, %1, %2, %3;" : "=f"(r) : "f"(v), "f"(m), "f"(v));
    return r;
}

// ============================================================
// prep: fragment-permuted f16 weights (single plane):
//   uint2 @ (L*CHUNK + ((kf*NF+nf)*32 + lane)*8) =
//     { W(k,k+1), W(k+8,k+9) }   all f16(w)
//   with n = nf*8 + lane/4, k = kf*16 + 2*(lane%4)
// bias (float2 per (nf,q)) @ L*CHUNK + BIASOFF + (nf*4+q)*8
// ============================================================
#define NWT (NLAYERS * KF * NF * 32)
__global__ void prep(const float* __restrict__ W_in, const float* __restrict__ b_in,
                     const float* __restrict__ Ws, const float* __restrict__ bs,
                     const float* __restrict__ W_out) {
    int t = blockIdx.x * 256 + threadIdx.x;
    if (t < NWT) {
        int L = t / (KF * NF * 32);
        int r = t % (KF * NF * 32);
        int kf = r / (NF * 32);
        int r2 = r % (NF * 32);
        int nf = r2 / 32, lane = r2 % 32;
        int n = nf * 8 + (lane >> 2);
        int k = kf * 16 + 2 * (lane & 3);
        float v[4];  // (k, k+1, k+8, k+9)
#pragma unroll
        for (int e = 0; e < 4; e++) {
            int kk = k + (e & 1) + (e >> 1) * 8;
            float w = 0.0f;
            if (L == 0) {
                if (kk < 64 && n < 100) w = W_in[kk * 100 + n];
            } else {
                if (kk < 100 && n < 100) w = Ws[((size_t)(L - 1) * 100 + kk) * 100 + n];
            }
            v[e] = w;
        }
        __half2 hp0 = __halves2half2(__float2half_rn(v[0]), __float2half_rn(v[1]));
        __half2 hp1 = __halves2half2(__float2half_rn(v[2]), __float2half_rn(v[3]));
        size_t off = (size_t)L * CHUNK + ((size_t)(kf * NF + nf) * 32 + lane) * 8;
        *(uint2*)(g_WP + off) = make_uint2(*(uint32_t*)&hp0, *(uint32_t*)&hp1);
        return;
    }
    t -= NWT;
    if (t < NLAYERS * NF * 4) {
        int m = t / (NF * 4);
        int r = t % (NF * 4);
        int nf = r / 4, q = r % 4;
        int c = nf * 8 + 2 * q;
        float b0 = (c < 100)     ? (m == 0 ? b_in[c]     : bs[(m - 1) * 100 + c])     : 0.0f;
        float b1 = (c + 1 < 100) ? (m == 0 ? b_in[c + 1] : bs[(m - 1) * 100 + c + 1]) : 0.0f;
        *(float2*)(g_WP + (size_t)m * CHUNK + BIASOFF + (size_t)r * 8) = make_float2(b0, b1);
        return;
    }
    t -= NLAYERS * NF * 4;
    if (t < NF * 4) {
        int nf = t / 4, q = t % 4;
        int c = nf * 8 + 2 * q;
        g_WOUTP[t] = make_float2(c < 100 ? W_out[c] : 0.0f,
                                 c + 1 < 100 ? W_out[c + 1] : 0.0f);
    }
}

// ============================================================
// main kernel: 128 threads, 4 warps x 32 samples = 128/block,
// occupancy 2, triple-buffered weights, mbarrier-only sync
// ============================================================
__global__ void __launch_bounds__(NT, 2)
actor(const float* __restrict__ x, const float* __restrict__ b_out,
      float* __restrict__ out, int nsamples) {
    extern __shared__ unsigned char sm[];
    const uint32_t smb = smem_u32(sm);
    const uint32_t mbF = smb + MBOFF;        // full[b] at +b*8
    const uint32_t mbE = smb + MBOFF + 24;   // free[b] at +b*8
    const int tid = threadIdx.x, lane = tid & 31, warp = tid >> 5;
    const int s0 = blockIdx.x * NT + warp * 32;
    const int r = lane >> 2, kc = 2 * (lane & 3);
    const bool v0 = (s0 + r)      < nsamples;
    const bool v1 = (s0 + r + 8)  < nsamples;
    const bool v2 = (s0 + r + 16) < nsamples;
    const bool v3 = (s0 + r + 24) < nsamples;

    // ---- mbarrier init (only __syncthreads in the kernel) ----
    if (tid == 0) {
#pragma unroll
        for (int b = 0; b < NBUF; b++) {
            mbar_init(mbF + b * 8, NT);   // 128 cp.async completions
            mbar_init(mbE + b * 8, NT);   // 128 thread arrivals
        }
    }
    __syncthreads();

    // ---- prologue: fill buffers 0..2 with layers 0..2 ----
#pragma unroll
    for (int L = 0; L < NBUF; L++) {
        const unsigned char* sp = g_WP + (size_t)L * CHUNK + tid * 16;
        uint32_t dp = smb + (uint32_t)L * CHUNK + tid * 16;
#pragma unroll
        for (int i = 0; i < CPITER; i++) cpa16(dp + i * (NT * 16), sp + (size_t)i * (NT * 16));
        cp_mbar_arrive(mbF + L * 8);
    }

    // ---- layer-0 A fragments (f16) straight from x (K=64 -> kf 0..3) ----
    uint32_t A0[KF][4], A1[KF][4];
    {
        const float* xb = x + (size_t)s0 * 64;
#pragma unroll
        for (int kf = 0; kf < 4; kf++) {
            int k = kf * 16 + kc;
            float2 pa0 = v0 ? *(const float2*)(xb + (size_t)r * 64 + k)            : make_float2(0.f, 0.f);
            float2 pa1 = v0 ? *(const float2*)(xb + (size_t)r * 64 + k + 8)        : make_float2(0.f, 0.f);
            float2 pb0 = v1 ? *(const float2*)(xb + (size_t)(r + 8) * 64 + k)      : make_float2(0.f, 0.f);
            float2 pb1 = v1 ? *(const float2*)(xb + (size_t)(r + 8) * 64 + k + 8)  : make_float2(0.f, 0.f);
            float2 pc0 = v2 ? *(const float2*)(xb + (size_t)(r + 16) * 64 + k)     : make_float2(0.f, 0.f);
            float2 pc1 = v2 ? *(const float2*)(xb + (size_t)(r + 16) * 64 + k + 8) : make_float2(0.f, 0.f);
            float2 pd0 = v3 ? *(const float2*)(xb + (size_t)(r + 24) * 64 + k)     : make_float2(0.f, 0.f);
            float2 pd1 = v3 ? *(const float2*)(xb + (size_t)(r + 24) * 64 + k + 8) : make_float2(0.f, 0.f);
            A0[kf][0] = packh(pa0.x, pa0.y);
            A0[kf][1] = packh(pb0.x, pb0.y);
            A0[kf][2] = packh(pa1.x, pa1.y);
            A0[kf][3] = packh(pb1.x, pb1.y);
            A1[kf][0] = packh(pc0.x, pc0.y);
            A1[kf][1] = packh(pd0.x, pd0.y);
            A1[kf][2] = packh(pc1.x, pc1.y);
            A1[kf][3] = packh(pd1.x, pd1.y);
        }
#pragma unroll
        for (int kf = 4; kf < KF; kf++) {
            A0[kf][0] = A0[kf][1] = A0[kf][2] = A0[kf][3] = 0u;
            A1[kf][0] = A1[kf][1] = A1[kf][2] = A1[kf][3] = 0u;
        }
    }

    float po0 = 0.0f, po1 = 0.0f, po2 = 0.0f, po3 = 0.0f;  // head partials

    int b = 0;         // buffer index = m % 3
    uint32_t par = 0;  // phase parity = (m/3) & 1 (shared schedule across buffers)

#pragma unroll 1
    for (int m = 0; m <= 100; m++) {
        const uint32_t bufA = smb + (uint32_t)b * CHUNK;

        // data ready? (cp.async completions from prologue or layer m-3)
        mbar_wait(mbF + b * 8, par);

        // D initialized to bias
        float D[NF][8];
        {
            uint32_t ba = bufA + BIASOFF + (uint32_t)(lane & 3) * 8;
#pragma unroll
            for (int nf = 0; nf < NF; nf++) {
                float2 bv = lds64f(ba + (uint32_t)nf * 32);
                D[nf][0] = bv.x; D[nf][1] = bv.y; D[nf][2] = bv.x; D[nf][3] = bv.y;
                D[nf][4] = bv.x; D[nf][5] = bv.y; D[nf][6] = bv.x; D[nf][7] = bv.y;
            }
        }

        // ---- single-product f16 GEMM: 1 LDS.64 feeds 2 HMMAs ----
#pragma unroll
        for (int kf = 0; kf < KF; kf++) {
            uint32_t ad = bufA + (uint32_t)(kf * NF) * 256 + lane * 8;
#pragma unroll
            for (int nf = 0; nf < NF; nf++) {
                uint2 w = lds64u(ad);
                hmma(&D[nf][0], A0[kf], w.x, w.y);   // A0 * W
                hmma(&D[nf][4], A1[kf], w.x, w.y);   // A1 * W
                ad += 256;
            }
        }

        // this thread is done reading buffer b
        mbar_arrive(mbE + b * 8);

        // ---- epilogue (registers only): leaky + f16 requantize ----
        if (m < 100) {
#pragma unroll
            for (int nf = 0; nf < NF; nf++) {
#pragma unroll
                for (int e = 0; e < 8; e++) D[nf][e] = leaky(D[nf][e]);
            }
#pragma unroll
            for (int t2 = 0; t2 < 6; t2++) {
                const float* d0 = D[2 * t2];
                const float* d1 = D[2 * t2 + 1];
                A0[t2][0] = packh(d0[0], d0[1]);
                A0[t2][1] = packh(d0[2], d0[3]);
                A0[t2][2] = packh(d1[0], d1[1]);
                A0[t2][3] = packh(d1[2], d1[3]);
                A1[t2][0] = packh(d0[4], d0[5]);
                A1[t2][1] = packh(d0[6], d0[7]);
                A1[t2][2] = packh(d1[4], d1[5]);
                A1[t2][3] = packh(d1[6], d1[7]);
            }
            {   // t2 = 6: cols 96..103 from D[12]; 104..111 zero-pad
                const float* d0 = D[12];
                A0[6][0] = packh(d0[0], d0[1]);
                A0[6][1] = packh(d0[2], d0[3]);
                A0[6][2] = 0u; A0[6][3] = 0u;
                A1[6][0] = packh(d0[4], d0[5]);
                A1[6][1] = packh(d0[6], d0[7]);
                A1[6][2] = 0u; A1[6][3] = 0u;
            }
        } else {
            // head: h = leaky(layer-100 out), partial dot with W_out
#pragma unroll
            for (int nf = 0; nf < NF; nf++) {
                float2 w = g_WOUTP[nf * 4 + (lane & 3)];
                po0 += leaky(D[nf][0]) * w.x + leaky(D[nf][1]) * w.y;
                po1 += leaky(D[nf][2]) * w.x + leaky(D[nf][3]) * w.y;
                po2 += leaky(D[nf][4]) * w.x + leaky(D[nf][5]) * w.y;
                po3 += leaky(D[nf][6]) * w.x + leaky(D[nf][7]) * w.y;
            }
        }

        // ---- refill buffer b with layer m+3 (after all reads done) ----
        if (m + 3 <= 100) {
            mbar_wait(mbE + b * 8, par);   // all 128 threads finished reading b
            const unsigned char* sp = g_WP + (size_t)(m + 3) * CHUNK + tid * 16;
            uint32_t dp = bufA + tid * 16;
#pragma unroll
            for (int i = 0; i < CPITER; i++) cpa16(dp + i * (NT * 16), sp + (size_t)i * (NT * 16));
            cp_mbar_arrive(mbF + b * 8);
        }

        if (++b == NBUF) { b = 0; par ^= 1u; }
    }

    // ---- head reduce across the 4 lanes sharing a row ----
    po0 += __shfl_xor_sync(0xffffffff, po0, 1);
    po0 += __shfl_xor_sync(0xffffffff, po0, 2);
    po1 += __shfl_xor_sync(0xffffffff, po1, 1);
    po1 += __shfl_xor_sync(0xffffffff, po1, 2);
    po2 += __shfl_xor_sync(0xffffffff, po2, 1);
    po2 += __shfl_xor_sync(0xffffffff, po2, 2);
    po3 += __shfl_xor_sync(0xffffffff, po3, 1);
    po3 += __shfl_xor_sync(0xffffffff, po3, 2);
    if ((lane & 3) == 0) {
        float bo = b_out[0];
        if (v0) out[s0 + r]      = tanhf(po0 + bo) * 4.5f + 5.5f;
        if (v1) out[s0 + r + 8]  = tanhf(po1 + bo) * 4.5f + 5.5f;
        if (v2) out[s0 + r + 16] = tanhf(po2 + bo) * 4.5f + 5.5f;
        if (v3) out[s0 + r + 24] = tanhf(po3 + bo) * 4.5f + 5.5f;
    }
}

extern "C" void kernel_launch(void* const* d_in, const int* in_sizes, int n_in,
                              void* d_out, int out_size) {
    const float* x     = (const float*)d_in[0];
    const float* W_in  = (const float*)d_in[1];
    const float* b_in  = (const float*)d_in[2];
    const float* Ws    = (const float*)d_in[3];
    const float* bs    = (const float*)d_in[4];
    const float* W_out = (const float*)d_in[5];
    const float* b_out = (const float*)d_in[6];
    float* out = (float*)d_out;

    int nsamples = in_sizes[0] / 64;
    int nblocks  = (nsamples + NT - 1) / NT;

    const int PREP_TOTAL = NWT + NLAYERS * NF * 4 + NF * 4;
    prep<<<(PREP_TOTAL + 255) / 256, 256>>>(W_in, b_in, Ws, bs, W_out);

    cudaFuncSetAttribute(actor, cudaFuncAttributeMaxDynamicSharedMemorySize, SMTOT);
    actor<<<nblocks, NT, SMTOT>>>(x, b_out, out, nsamples);
}

// round 16
// speedup vs baseline: 3.4522x; 1.1485x over previous
#include <cuda_runtime.h>
#include <cuda_fp16.h>
#include <cstdint>

// ============================================================
// Actor MLP via warp-level mma.sync, single-product f16 GEMM:
//   D = Af16 * Wf16   (fp32 accum)
// R16: (a) epilogue in packed f16: requantize first, then
//   leaky(x)=max(x,0.01x) via mul.f16x2+max.f16x2 (halves the
//   serial epilogue chain); (b) nf-pair-contiguous weight
//   layout -> one LDS.128 feeds 4 HMMAs. GEMM accumulation
//   order identical to R15. mbarrier triple-buffer pipeline.
// 128-thread blocks (4 warps x 32 samples), occupancy 2.
// ============================================================

#define NF 13          // n-fragments (8 wide)  -> N = 104
#define KF 7           // k-fragments (16 wide) -> K = 112
#define CHUNK 24576    // per-layer chunk stride; weights 23296B + bias 416B
#define PAIRREG 21504  // nf-pair region: 7*6*512
#define TAILOFF 21504  // nf=12 tail region: 7*256 = 1792 (ends at 23296)
#define BIASOFF 23296  // bias offset inside chunk
#define NLAYERS 101    // layer 0 = W_in, layers 1..100 = hidden
#define NT 128         // threads per block (4 warps x 32 samples)
#define NBUF 3
#define CPITER (CHUNK / (NT * 16))   // 12 cp.async iters per chunk per thread
#define MBOFF (NBUF * CHUNK)
#define SMTOT (MBOFF + 64)
#define C01X2 0x211F211Fu            // f16x2 {0.01, 0.01}

__device__ __align__(16) unsigned char g_WP[NLAYERS * CHUNK];    // ~2.48 MB
__device__ __align__(16) float2 g_WOUTP[NF * 4];

// ---- helpers ----
__device__ __forceinline__ uint32_t smem_u32(const void* p) {
    uint32_t a;
    asm("{ .reg .u64 t; cvta.to.shared.u64 t, %1; cvt.u32.u64 %0, t; }" : "=r"(a) : "l"(p));
    return a;
}
// pack {lower=lo_val, upper=hi_val} as f16x2 (cvt: first src -> upper half)
__device__ __forceinline__ uint32_t packh(float lo_val, float hi_val) {
    uint32_t r;
    asm("cvt.rn.f16x2.f32 %0, %1, %2;" : "=r"(r) : "f"(hi_val), "f"(lo_val));
    return r;
}
// requantize + leaky in f16x2: q=pack(a,b); max(q, 0.01*q)
__device__ __forceinline__ uint32_t leakyq(float a, float b) {
    uint32_t q = packh(a, b), m, r;
    asm("mul.f16x2 %0, %1, %2;" : "=r"(m) : "r"(q), "r"(C01X2));
    asm("max.f16x2 %0, %1, %2;" : "=r"(r) : "r"(q), "r"(m));
    return r;
}
__device__ __forceinline__ uint4 lds128(uint32_t a) {
    uint4 v;
    asm("ld.shared.v4.u32 {%0,%1,%2,%3}, [%4];"
        : "=r"(v.x), "=r"(v.y), "=r"(v.z), "=r"(v.w) : "r"(a));
    return v;
}
__device__ __forceinline__ uint2 lds64u(uint32_t a) {
    uint2 v;
    asm("ld.shared.v2.u32 {%0,%1}, [%2];" : "=r"(v.x), "=r"(v.y) : "r"(a));
    return v;
}
__device__ __forceinline__ float2 lds64f(uint32_t a) {
    float2 v;
    asm("ld.shared.v2.f32 {%0,%1}, [%2];" : "=f"(v.x), "=f"(v.y) : "r"(a));
    return v;
}
__device__ __forceinline__ void cpa16(uint32_t dst, const void* src) {
    asm volatile("cp.async.cg.shared.global [%0], [%1], 16;" :: "r"(dst), "l"(src) : "memory");
}
// ---- mbarrier primitives (sm_80/90 baseline) ----
__device__ __forceinline__ void mbar_init(uint32_t a, uint32_t cnt) {
    asm volatile("mbarrier.init.shared.b64 [%0], %1;" :: "r"(a), "r"(cnt) : "memory");
}
__device__ __forceinline__ void mbar_arrive(uint32_t a) {
    unsigned long long st;
    asm volatile("mbarrier.arrive.shared.b64 %0, [%1];" : "=l"(st) : "r"(a) : "memory");
}
__device__ __forceinline__ void mbar_wait(uint32_t a, uint32_t par) {
    asm volatile(
        "{\n\t.reg .pred P;\n\t"
        "WL%=:\n\t"
        "mbarrier.try_wait.parity.shared.b64 P, [%0], %1, 0x989680;\n\t"
        "@!P bra WL%=;\n\t}"
        :: "r"(a), "r"(par) : "memory");
}
__device__ __forceinline__ void cp_mbar_arrive(uint32_t a) {
    asm volatile("cp.async.mbarrier.arrive.noinc.shared.b64 [%0];" :: "r"(a) : "memory");
}

__device__ __forceinline__ void hmma(float* d, const uint32_t* a, uint32_t b0, uint32_t b1) {
    asm("mma.sync.aligned.m16n8k16.row.col.f32.f16.f16.f32 "
        "{%0,%1,%2,%3}, {%4,%5,%6,%7}, {%8,%9}, {%0,%1,%2,%3};"
        : "+f"(d[0]), "+f"(d[1]), "+f"(d[2]), "+f"(d[3])
        : "r"(a[0]), "r"(a[1]), "r"(a[2]), "r"(a[3]), "r"(b0), "r"(b1));
}
// fp32 leaky (head layer only)
__device__ __forceinline__ float leaky(float v) {
    float m = 0.01f * v, r;
    asm("slct.f32.f32 %0, %1, %2, %3;" : "=f"(r) : "f"(v), "f"(m), "f"(v));
    return r;
}

// ============================================================
// prep: fragment-permuted f16 weights, nf-PAIR contiguous:
//  nf<12: uint4 @ L*CHUNK + (kf*6 + nf/2)*512 + lane*16 + (nf&1)*8
//         = { Wnf(k,k+1), Wnf(k+8,k+9) } in its half
//  nf=12: uint2 @ L*CHUNK + TAILOFF + kf*256 + lane*8
//  with n = nf*8 + lane/4, k = kf*16 + 2*(lane%4)
// bias (float2 per (nf,q)) @ L*CHUNK + BIASOFF + (nf*4+q)*8
// ============================================================
#define NWT (NLAYERS * KF * NF * 32)
__global__ void prep(const float* __restrict__ W_in, const float* __restrict__ b_in,
                     const float* __restrict__ Ws, const float* __restrict__ bs,
                     const float* __restrict__ W_out) {
    int t = blockIdx.x * 256 + threadIdx.x;
    if (t < NWT) {
        int L = t / (KF * NF * 32);
        int r = t % (KF * NF * 32);
        int kf = r / (NF * 32);
        int r2 = r % (NF * 32);
        int nf = r2 / 32, lane = r2 % 32;
        int n = nf * 8 + (lane >> 2);
        int k = kf * 16 + 2 * (lane & 3);
        float v[4];  // (k, k+1, k+8, k+9)
#pragma unroll
        for (int e = 0; e < 4; e++) {
            int kk = k + (e & 1) + (e >> 1) * 8;
            float w = 0.0f;
            if (L == 0) {
                if (kk < 64 && n < 100) w = W_in[kk * 100 + n];
            } else {
                if (kk < 100 && n < 100) w = Ws[((size_t)(L - 1) * 100 + kk) * 100 + n];
            }
            v[e] = w;
        }
        __half2 hp0 = __halves2half2(__float2half_rn(v[0]), __float2half_rn(v[1]));
        __half2 hp1 = __halves2half2(__float2half_rn(v[2]), __float2half_rn(v[3]));
        size_t off;
        if (nf < 12) {
            off = (size_t)L * CHUNK + ((size_t)(kf * 6 + (nf >> 1)) * 512)
                + (size_t)lane * 16 + (size_t)(nf & 1) * 8;
        } else {
            off = (size_t)L * CHUNK + TAILOFF + (size_t)kf * 256 + (size_t)lane * 8;
        }
        *(uint2*)(g_WP + off) = make_uint2(*(uint32_t*)&hp0, *(uint32_t*)&hp1);
        return;
    }
    t -= NWT;
    if (t < NLAYERS * NF * 4) {
        int m = t / (NF * 4);
        int r = t % (NF * 4);
        int nf = r / 4, q = r % 4;
        int c = nf * 8 + 2 * q;
        float b0 = (c < 100)     ? (m == 0 ? b_in[c]     : bs[(m - 1) * 100 + c])     : 0.0f;
        float b1 = (c + 1 < 100) ? (m == 0 ? b_in[c + 1] : bs[(m - 1) * 100 + c + 1]) : 0.0f;
        *(float2*)(g_WP + (size_t)m * CHUNK + BIASOFF + (size_t)r * 8) = make_float2(b0, b1);
        return;
    }
    t -= NLAYERS * NF * 4;
    if (t < NF * 4) {
        int nf = t / 4, q = t % 4;
        int c = nf * 8 + 2 * q;
        g_WOUTP[t] = make_float2(c < 100 ? W_out[c] : 0.0f,
                                 c + 1 < 100 ? W_out[c + 1] : 0.0f);
    }
}

// ============================================================
// main kernel: 128 threads, 4 warps x 32 samples = 128/block,
// occupancy 2, triple-buffered weights, mbarrier-only sync
// ============================================================
__global__ void __launch_bounds__(NT, 2)
actor(const float* __restrict__ x, const float* __restrict__ b_out,
      float* __restrict__ out, int nsamples) {
    extern __shared__ unsigned char sm[];
    const uint32_t smb = smem_u32(sm);
    const uint32_t mbF = smb + MBOFF;        // full[b] at +b*8
    const uint32_t mbE = smb + MBOFF + 24;   // free[b] at +b*8
    const int tid = threadIdx.x, lane = tid & 31, warp = tid >> 5;
    const int s0 = blockIdx.x * NT + warp * 32;
    const int r = lane >> 2, kc = 2 * (lane & 3);
    const bool v0 = (s0 + r)      < nsamples;
    const bool v1 = (s0 + r + 8)  < nsamples;
    const bool v2 = (s0 + r + 16) < nsamples;
    const bool v3 = (s0 + r + 24) < nsamples;

    if (tid == 0) {
#pragma unroll
        for (int b = 0; b < NBUF; b++) {
            mbar_init(mbF + b * 8, NT);
            mbar_init(mbE + b * 8, NT);
        }
    }
    __syncthreads();

    // ---- prologue: fill buffers 0..2 with layers 0..2 ----
#pragma unroll
    for (int L = 0; L < NBUF; L++) {
        const unsigned char* sp = g_WP + (size_t)L * CHUNK + tid * 16;
        uint32_t dp = smb + (uint32_t)L * CHUNK + tid * 16;
#pragma unroll
        for (int i = 0; i < CPITER; i++) cpa16(dp + i * (NT * 16), sp + (size_t)i * (NT * 16));
        cp_mbar_arrive(mbF + L * 8);
    }

    // ---- layer-0 A fragments (f16) straight from x ----
    uint32_t A0[KF][4], A1[KF][4];
    {
        const float* xb = x + (size_t)s0 * 64;
#pragma unroll
        for (int kf = 0; kf < 4; kf++) {
            int k = kf * 16 + kc;
            float2 pa0 = v0 ? *(const float2*)(xb + (size_t)r * 64 + k)            : make_float2(0.f, 0.f);
            float2 pa1 = v0 ? *(const float2*)(xb + (size_t)r * 64 + k + 8)        : make_float2(0.f, 0.f);
            float2 pb0 = v1 ? *(const float2*)(xb + (size_t)(r + 8) * 64 + k)      : make_float2(0.f, 0.f);
            float2 pb1 = v1 ? *(const float2*)(xb + (size_t)(r + 8) * 64 + k + 8)  : make_float2(0.f, 0.f);
            float2 pc0 = v2 ? *(const float2*)(xb + (size_t)(r + 16) * 64 + k)     : make_float2(0.f, 0.f);
            float2 pc1 = v2 ? *(const float2*)(xb + (size_t)(r + 16) * 64 + k + 8) : make_float2(0.f, 0.f);
            float2 pd0 = v3 ? *(const float2*)(xb + (size_t)(r + 24) * 64 + k)     : make_float2(0.f, 0.f);
            float2 pd1 = v3 ? *(const float2*)(xb + (size_t)(r + 24) * 64 + k + 8) : make_float2(0.f, 0.f);
            A0[kf][0] = packh(pa0.x, pa0.y);
            A0[kf][1] = packh(pb0.x, pb0.y);
            A0[kf][2] = packh(pa1.x, pa1.y);
            A0[kf][3] = packh(pb1.x, pb1.y);
            A1[kf][0] = packh(pc0.x, pc0.y);
            A1[kf][1] = packh(pd0.x, pd0.y);
            A1[kf][2] = packh(pc1.x, pc1.y);
            A1[kf][3] = packh(pd1.x, pd1.y);
        }
#pragma unroll
        for (int kf = 4; kf < KF; kf++) {
            A0[kf][0] = A0[kf][1] = A0[kf][2] = A0[kf][3] = 0u;
            A1[kf][0] = A1[kf][1] = A1[kf][2] = A1[kf][3] = 0u;
        }
    }

    float po0 = 0.0f, po1 = 0.0f, po2 = 0.0f, po3 = 0.0f;

    int b = 0;
    uint32_t par = 0;

#pragma unroll 1
    for (int m = 0; m <= 100; m++) {
        const uint32_t bufA = smb + (uint32_t)b * CHUNK;

        mbar_wait(mbF + b * 8, par);

        // D initialized to bias
        float D[NF][8];
        {
            uint32_t ba = bufA + BIASOFF + (uint32_t)(lane & 3) * 8;
#pragma unroll
            for (int nf = 0; nf < NF; nf++) {
                float2 bv = lds64f(ba + (uint32_t)nf * 32);
                D[nf][0] = bv.x; D[nf][1] = bv.y; D[nf][2] = bv.x; D[nf][3] = bv.y;
                D[nf][4] = bv.x; D[nf][5] = bv.y; D[nf][6] = bv.x; D[nf][7] = bv.y;
            }
        }

        // ---- single-product f16 GEMM: LDS.128 feeds 4 HMMAs ----
        // accumulation order per D[nf]: kf ascending (identical to R15)
#pragma unroll
        for (int kf = 0; kf < KF; kf++) {
            uint32_t adp = bufA + (uint32_t)(kf * 6) * 512 + lane * 16;
#pragma unroll
            for (int np = 0; np < 6; np++) {
                uint4 w = lds128(adp);
                hmma(&D[2*np][0],   A0[kf], w.x, w.y);
                hmma(&D[2*np][4],   A1[kf], w.x, w.y);
                hmma(&D[2*np+1][0], A0[kf], w.z, w.w);
                hmma(&D[2*np+1][4], A1[kf], w.z, w.w);
                adp += 512;
            }
            {   // nf = 12 tail
                uint2 wt = lds64u(bufA + TAILOFF + (uint32_t)kf * 256 + lane * 8);
                hmma(&D[12][0], A0[kf], wt.x, wt.y);
                hmma(&D[12][4], A1[kf], wt.x, wt.y);
            }
        }

        mbar_arrive(mbE + b * 8);

        // ---- epilogue: requantize + packed-f16 leaky ----
        if (m < 100) {
#pragma unroll
            for (int t2 = 0; t2 < 6; t2++) {
                const float* d0 = D[2 * t2];
                const float* d1 = D[2 * t2 + 1];
                A0[t2][0] = leakyq(d0[0], d0[1]);
                A0[t2][1] = leakyq(d0[2], d0[3]);
                A0[t2][2] = leakyq(d1[0], d1[1]);
                A0[t2][3] = leakyq(d1[2], d1[3]);
                A1[t2][0] = leakyq(d0[4], d0[5]);
                A1[t2][1] = leakyq(d0[6], d0[7]);
                A1[t2][2] = leakyq(d1[4], d1[5]);
                A1[t2][3] = leakyq(d1[6], d1[7]);
            }
            {   // t2 = 6: cols 96..103 from D[12]; 104..111 zero-pad
                const float* d0 = D[12];
                A0[6][0] = leakyq(d0[0], d0[1]);
                A0[6][1] = leakyq(d0[2], d0[3]);
                A0[6][2] = 0u; A0[6][3] = 0u;
                A1[6][0] = leakyq(d0[4], d0[5]);
                A1[6][1] = leakyq(d0[6], d0[7]);
                A1[6][2] = 0u; A1[6][3] = 0u;
            }
        } else {
            // head: fp32 leaky + dot with W_out (unchanged numerics)
#pragma unroll
            for (int nf = 0; nf < NF; nf++) {
                float2 w = g_WOUTP[nf * 4 + (lane & 3)];
                po0 += leaky(D[nf][0]) * w.x + leaky(D[nf][1]) * w.y;
                po1 += leaky(D[nf][2]) * w.x + leaky(D[nf][3]) * w.y;
                po2 += leaky(D[nf][4]) * w.x + leaky(D[nf][5]) * w.y;
                po3 += leaky(D[nf][6]) * w.x + leaky(D[nf][7]) * w.y;
            }
        }

        // ---- refill buffer b with layer m+3 ----
        if (m + 3 <= 100) {
            mbar_wait(mbE + b * 8, par);
            const unsigned char* sp = g_WP + (size_t)(m + 3) * CHUNK + tid * 16;
            uint32_t dp = bufA + tid * 16;
#pragma unroll
            for (int i = 0; i < CPITER; i++) cpa16(dp + i * (NT * 16), sp + (size_t)i * (NT * 16));
            cp_mbar_arrive(mbF + b * 8);
        }

        if (++b == NBUF) { b = 0; par ^= 1u; }
    }

    // ---- head reduce across the 4 lanes sharing a row ----
    po0 += __shfl_xor_sync(0xffffffff, po0, 1);
    po0 += __shfl_xor_sync(0xffffffff, po0, 2);
    po1 += __shfl_xor_sync(0xffffffff, po1, 1);
    po1 += __shfl_xor_sync(0xffffffff, po1, 2);
    po2 += __shfl_xor_sync(0xffffffff, po2, 1);
    po2 += __shfl_xor_sync(0xffffffff, po2, 2);
    po3 += __shfl_xor_sync(0xffffffff, po3, 1);
    po3 += __shfl_xor_sync(0xffffffff, po3, 2);
    if ((lane & 3) == 0) {
        float bo = b_out[0];
        if (v0) out[s0 + r]      = tanhf(po0 + bo) * 4.5f + 5.5f;
        if (v1) out[s0 + r + 8]  = tanhf(po1 + bo) * 4.5f + 5.5f;
        if (v2) out[s0 + r + 16] = tanhf(po2 + bo) * 4.5f + 5.5f;
        if (v3) out[s0 + r + 24] = tanhf(po3 + bo) * 4.5f + 5.5f;
    }
}

extern "C" void kernel_launch(void* const* d_in, const int* in_sizes, int n_in,
                              void* d_out, int out_size) {
    const float* x     = (const float*)d_in[0];
    const float* W_in  = (const float*)d_in[1];
    const float* b_in  = (const float*)d_in[2];
    const float* Ws    = (const float*)d_in[3];
    const float* bs    = (const float*)d_in[4];
    const float* W_out = (const float*)d_in[5];
    const float* b_out = (const float*)d_in[6];
    float* out = (float*)d_out;

    int nsamples = in_sizes[0] / 64;
    int nblocks  = (nsamples + NT - 1) / NT;

    const int PREP_TOTAL = NWT + NLAYERS * NF * 4 + NF * 4;
    prep<<<(PREP_TOTAL + 255) / 256, 256>>>(W_in, b_in, Ws, bs, W_out);

    cudaFuncSetAttribute(actor, cudaFuncAttributeMaxDynamicSharedMemorySize, SMTOT);
    actor<<<nblocks, NT, SMTOT>>>(x, b_out, out, nsamples);
}